// round 14
// baseline (speedup 1.0000x reference)
#include <cuda_runtime.h>
#include <cuda_bf16.h>
#include <math.h>
#include <stdint.h>

// B=8 S=512 FDIM=512 SUB=4 DIM=128 HEADS=8 DH=64 INNER=512
// T=2176 (2048+128 mem), NB=34, N_HASHES=4, BUCKET=64, C=136, 4T=8704

__device__ float g_x1 [8*2048*128];
__device__ float g_x2 [8*2048*128];
__device__ float g_fin[8*2048*128];
__device__ __nv_bfloat16 g_aqh[8*2176*128];      // qkv input hi
__device__ __nv_bfloat16 g_aql[8*2176*128];      // qkv input lo
__device__ __nv_bfloat16 g_ain[8*2048*128];      // bf16 ff1 input
__device__ __nv_bfloat16 g_am [8*2048*512];      // bf16 merged attention output
__device__ __nv_bfloat16 g_ff [8*2048*512];      // bf16 gelu output
__device__ float g_qk [8*8*2176*64];
__device__ float g_v  [8*8*2176*64];
__device__ int   g_bkt [48*8704];
__device__ int   g_st  [48*8704];
__device__ int   g_undo[48*8704];
__device__ float g_so  [48*8704*64];
__device__ float g_slog[48*8704];
__device__ __nv_bfloat16 g_wt_out[2][128*512];   // w_out^T  [n=128][k=512]
__device__ __nv_bfloat16 g_wt_ff1[2][512*128];   // ff_w1^T  [n=512][k=128]
__device__ __nv_bfloat16 g_wt_ff2[2][128*512];   // ff_w2^T  [n=128][k=512]
__device__ __nv_bfloat16 g_wqk_h[2][512*128];    // w_qk^T hi [n=512][k=128]
__device__ __nv_bfloat16 g_wqk_l[2][512*128];    // w_qk^T lo
__device__ __nv_bfloat16 g_wv_h [2][512*128];
__device__ __nv_bfloat16 g_wv_l [2][512*128];

__device__ __forceinline__ uint32_t smem_u32(const void* p){
    uint32_t a;
    asm("{ .reg .u64 t; cvta.to.shared.u64 t, %1; cvt.u32.u64 %0, t; }" : "=r"(a) : "l"(p));
    return a;
}
__device__ __forceinline__ void ldm4(uint32_t& r0, uint32_t& r1, uint32_t& r2, uint32_t& r3,
                                     uint32_t addr){
    asm volatile("ldmatrix.sync.aligned.m8n8.x4.shared.b16 {%0,%1,%2,%3}, [%4];"
        : "=r"(r0),"=r"(r1),"=r"(r2),"=r"(r3) : "r"(addr));
}
__device__ __forceinline__ void ldm4t(uint32_t& r0, uint32_t& r1, uint32_t& r2, uint32_t& r3,
                                      uint32_t addr){
    asm volatile("ldmatrix.sync.aligned.m8n8.x4.trans.shared.b16 {%0,%1,%2,%3}, [%4];"
        : "=r"(r0),"=r"(r1),"=r"(r2),"=r"(r3) : "r"(addr));
}
__device__ __forceinline__ void mma16816(float* c, const uint32_t* a, const uint32_t* b){
    asm volatile("mma.sync.aligned.m16n8k16.row.col.f32.bf16.bf16.f32 "
        "{%0,%1,%2,%3}, {%4,%5,%6,%7}, {%8,%9}, {%0,%1,%2,%3};"
        : "+f"(c[0]),"+f"(c[1]),"+f"(c[2]),"+f"(c[3])
        : "r"(a[0]),"r"(a[1]),"r"(a[2]),"r"(a[3]), "r"(b[0]),"r"(b[1]));
}
__device__ __forceinline__ uint4 f8_to_bf8(float4 a, float4 b){
    __nv_bfloat162 h0 = __floats2bfloat162_rn(a.x, a.y);
    __nv_bfloat162 h1 = __floats2bfloat162_rn(a.z, a.w);
    __nv_bfloat162 h2 = __floats2bfloat162_rn(b.x, b.y);
    __nv_bfloat162 h3 = __floats2bfloat162_rn(b.z, b.w);
    uint4 r;
    r.x = *(uint32_t*)&h0; r.y = *(uint32_t*)&h1;
    r.z = *(uint32_t*)&h2; r.w = *(uint32_t*)&h3;
    return r;
}

// ---- weight convert+transpose: fp32 [K][N] -> bf16 [N][K] ----
__global__ void __launch_bounds__(256) k_wcvt(const float* __restrict__ in,
                                              __nv_bfloat16* __restrict__ out,
                                              int K, int N){
    int idx = blockIdx.x*256 + threadIdx.x;
    int n = idx / K, k = idx - n*K;
    out[idx] = __float2bfloat16(in[k*N + n]);
}
// ---- split weight convert+transpose: fp32 [K][N] -> hi/lo bf16 [N][K] ----
__global__ void __launch_bounds__(256) k_wcvt2(const float* __restrict__ in,
                                               __nv_bfloat16* __restrict__ oh,
                                               __nv_bfloat16* __restrict__ ol,
                                               int K, int N){
    int idx = blockIdx.x*256 + threadIdx.x;
    int n = idx / K, k = idx - n*K;
    float x = in[k*N + n];
    __nv_bfloat16 h = __float2bfloat16(x);
    oh[idx] = h;
    ol[idx] = __float2bfloat16(x - __bfloat162float(h));
}

// ====== HMMA GEMM: C[M,N] = A[M,K](bf16) * BT[N,K]^T, fp32 epilogue ======
struct EAddBias {
    float* out; const float* bias; int ld;
    __device__ __forceinline__ void operator()(int m, int n, float v) const {
        out[m*ld + n] += v + bias[n];
    }
};
struct EGelu {
    __nv_bfloat16* out; const float* bias;
    __device__ __forceinline__ void operator()(int m, int n, float v) const {
        float h = v + bias[n];
        out[m*512 + n] = __float2bfloat16(0.5f*h*(1.0f + erff(h*0.7071067811865475f)));
    }
};
struct EQKV {
    float* out;
    __device__ __forceinline__ void operator()(int m, int n, float v) const {
        int b = m / 2176, t = m - b*2176;
        out[(((b<<3) + (n>>6))*2176 + t)*64 + (n & 63)] = v;
    }
};

template<class EP>
__global__ void __launch_bounds__(256) k_tgemm(const __nv_bfloat16* __restrict__ A, int K,
                                               const __nv_bfloat16* __restrict__ BT,
                                               EP ep){
    __shared__ __nv_bfloat16 As[128][72];
    __shared__ __nv_bfloat16 Bs[128][72];
    int tid = threadIdx.x, wid = tid >> 5, lane = tid & 31;
    int wm = wid >> 1, wn = wid & 1;
    int bm = blockIdx.y*128, bn = blockIdx.x*128;
    float acc[2][8][4] = {};
    int nc = K >> 6;
    for (int kc = 0; kc < nc; kc++){
        for (int p = tid; p < 1024; p += 256){
            int row = p >> 3, q = p & 7;
            *(uint4*)&As[row][q*8] = *(const uint4*)(A  + (size_t)(bm+row)*K + kc*64 + q*8);
            *(uint4*)&Bs[row][q*8] = *(const uint4*)(BT + (size_t)(bn+row)*K + kc*64 + q*8);
        }
        __syncthreads();
#pragma unroll
        for (int s = 0; s < 4; s++){
            uint32_t af[2][4];
#pragma unroll
            for (int mt = 0; mt < 2; mt++){
                uint32_t addr = smem_u32(&As[wm*32 + mt*16 + (lane & 15)][s*16 + (lane >> 4)*8]);
                ldm4(af[mt][0], af[mt][1], af[mt][2], af[mt][3], addr);
            }
            uint32_t bf[8][2];
#pragma unroll
            for (int nt16 = 0; nt16 < 4; nt16++){
                int mi = lane >> 3;
                uint32_t addr = smem_u32(&Bs[wn*64 + nt16*16 + (mi >> 1)*8 + (lane & 7)][s*16 + (mi & 1)*8]);
                uint32_t r0,r1,r2,r3;
                ldm4(r0,r1,r2,r3, addr);
                bf[nt16*2][0]   = r0; bf[nt16*2][1]   = r1;
                bf[nt16*2+1][0] = r2; bf[nt16*2+1][1] = r3;
            }
#pragma unroll
            for (int mt = 0; mt < 2; mt++)
#pragma unroll
                for (int nt = 0; nt < 8; nt++)
                    mma16816(acc[mt][nt], af[mt], bf[nt]);
        }
        __syncthreads();
    }
#pragma unroll
    for (int mt = 0; mt < 2; mt++){
#pragma unroll
        for (int nt = 0; nt < 8; nt++){
            int m = bm + wm*32 + mt*16 + (lane >> 2);
            int n = bn + wn*64 + nt*8 + (lane & 3)*2;
            ep(m,   n,   acc[mt][nt][0]);
            ep(m,   n+1, acc[mt][nt][1]);
            ep(m+8, n,   acc[mt][nt][2]);
            ep(m+8, n+1, acc[mt][nt][3]);
        }
    }
}

// ====== split-bf16 3-term GEMM (fp32-accurate-ish): C = Ah*Bh + Ah*Bl + Al*Bh ======
// A hi/lo [M][128], BT hi/lo [N][128]. Tile 128x128, K=128 (2 chunks of 64).
__global__ void __launch_bounds__(256) k_tgemm3(const __nv_bfloat16* __restrict__ Ah,
                                                const __nv_bfloat16* __restrict__ Al,
                                                const __nv_bfloat16* __restrict__ BTh,
                                                const __nv_bfloat16* __restrict__ BTl,
                                                EQKV ep){
    extern __shared__ char smc[];
    __nv_bfloat16* Ash = (__nv_bfloat16*)smc;              // [128][72]
    __nv_bfloat16* Asl = (__nv_bfloat16*)(smc + 18432);
    __nv_bfloat16* Bsh = (__nv_bfloat16*)(smc + 36864);
    __nv_bfloat16* Bsl = (__nv_bfloat16*)(smc + 55296);
    const int K = 128;
    int tid = threadIdx.x, wid = tid >> 5, lane = tid & 31;
    int wm = wid >> 1, wn = wid & 1;
    int bm = blockIdx.y*128, bn = blockIdx.x*128;
    float acc[2][8][4] = {};
    for (int kc = 0; kc < 2; kc++){
        for (int p = tid; p < 1024; p += 256){
            int row = p >> 3, q = p & 7;
            size_t ga = (size_t)(bm+row)*K + kc*64 + q*8;
            size_t gb = (size_t)(bn+row)*K + kc*64 + q*8;
            *(uint4*)&Ash[row*72 + q*8] = *(const uint4*)(Ah  + ga);
            *(uint4*)&Asl[row*72 + q*8] = *(const uint4*)(Al  + ga);
            *(uint4*)&Bsh[row*72 + q*8] = *(const uint4*)(BTh + gb);
            *(uint4*)&Bsl[row*72 + q*8] = *(const uint4*)(BTl + gb);
        }
        __syncthreads();
#pragma unroll
        for (int s = 0; s < 4; s++){
            uint32_t afh[2][4], afl[2][4];
#pragma unroll
            for (int mt = 0; mt < 2; mt++){
                int ro = (wm*32 + mt*16 + (lane & 15))*72 + s*16 + (lane >> 4)*8;
                ldm4(afh[mt][0], afh[mt][1], afh[mt][2], afh[mt][3], smem_u32(&Ash[ro]));
                ldm4(afl[mt][0], afl[mt][1], afl[mt][2], afl[mt][3], smem_u32(&Asl[ro]));
            }
            uint32_t bfh[8][2], bfl[8][2];
#pragma unroll
            for (int nt16 = 0; nt16 < 4; nt16++){
                int mi = lane >> 3;
                int ro = (wn*64 + nt16*16 + (mi >> 1)*8 + (lane & 7))*72 + s*16 + (mi & 1)*8;
                uint32_t r0,r1,r2,r3;
                ldm4(r0,r1,r2,r3, smem_u32(&Bsh[ro]));
                bfh[nt16*2][0] = r0; bfh[nt16*2][1] = r1;
                bfh[nt16*2+1][0] = r2; bfh[nt16*2+1][1] = r3;
                ldm4(r0,r1,r2,r3, smem_u32(&Bsl[ro]));
                bfl[nt16*2][0] = r0; bfl[nt16*2][1] = r1;
                bfl[nt16*2+1][0] = r2; bfl[nt16*2+1][1] = r3;
            }
#pragma unroll
            for (int mt = 0; mt < 2; mt++)
#pragma unroll
                for (int nt = 0; nt < 8; nt++){
                    mma16816(acc[mt][nt], afh[mt], bfh[nt]);
                    mma16816(acc[mt][nt], afh[mt], bfl[nt]);
                    mma16816(acc[mt][nt], afl[mt], bfh[nt]);
                }
        }
        __syncthreads();
    }
#pragma unroll
    for (int mt = 0; mt < 2; mt++){
#pragma unroll
        for (int nt = 0; nt < 8; nt++){
            int m = bm + wm*32 + mt*16 + (lane >> 2);
            int n = bn + wn*64 + nt*8 + (lane & 3)*2;
            ep(m,   n,   acc[mt][nt][0]);
            ep(m,   n+1, acc[mt][nt][1]);
            ep(m+8, n,   acc[mt][nt][2]);
            ep(m+8, n+1, acc[mt][nt][3]);
        }
    }
}

// ================= rest of pipeline =================
__global__ void __launch_bounds__(256) k_embed(const float* __restrict__ feat){
    int idx = blockIdx.x*256 + threadIdx.x;
    int b = idx >> 18, r = idx & 262143;
    int t = r >> 7, d = r & 127;
    int s = t >> 2, f = ((t & 3) << 7) + d;
    float inv = expf(-(2.0f*(float)f/512.0f)*9.210340371976184f);
    float ang = (float)s * inv;
    float pe = (f & 1) ? cosf(ang) : sinf(ang);
    float v = feat[(b*512 + s)*512 + f] + pe;
    g_x1[idx] = v; g_x2[idx] = v;
}

template<typename OutT>
__global__ void __launch_bounds__(128) k_layernorm(const float* __restrict__ in1,
                                                   const float* __restrict__ in2,
                                                   OutT* __restrict__ outp,
                                                   const float* __restrict__ gam,
                                                   const float* __restrict__ bet){
    int row = blockIdx.x, d = threadIdx.x;
    float x = in1[row*128 + d];
    if (in2) x = 0.5f*(x + in2[row*128 + d]);
    __shared__ float sh[4];
    float s = x;
#pragma unroll
    for (int o=16;o>0;o>>=1) s += __shfl_xor_sync(0xffffffffu, s, o);
    if ((d & 31) == 0) sh[d>>5] = s;
    __syncthreads();
    float mean = (sh[0]+sh[1]+sh[2]+sh[3]) * (1.0f/128.0f);
    float c = x - mean;
    __syncthreads();
    float v = c*c;
#pragma unroll
    for (int o=16;o>0;o>>=1) v += __shfl_xor_sync(0xffffffffu, v, o);
    if ((d & 31) == 0) sh[d>>5] = v;
    __syncthreads();
    float var = (sh[0]+sh[1]+sh[2]+sh[3]) * (1.0f/128.0f);
    outp[row*128 + d] = (OutT)(c * rsqrtf(var + 1e-5f) * gam[d] + bet[d]);
}

// LN -> packed split hi/lo (rows b*2048+t -> b*2176+t)
__global__ void __launch_bounds__(128) k_ln_split(const float* __restrict__ in1,
                                                  __nv_bfloat16* __restrict__ oh,
                                                  __nv_bfloat16* __restrict__ ol,
                                                  const float* __restrict__ gam,
                                                  const float* __restrict__ bet){
    int row = blockIdx.x, d = threadIdx.x;
    float x = in1[row*128 + d];
    __shared__ float sh[4];
    float s = x;
#pragma unroll
    for (int o=16;o>0;o>>=1) s += __shfl_xor_sync(0xffffffffu, s, o);
    if ((d & 31) == 0) sh[d>>5] = s;
    __syncthreads();
    float mean = (sh[0]+sh[1]+sh[2]+sh[3]) * (1.0f/128.0f);
    float c = x - mean;
    __syncthreads();
    float v = c*c;
#pragma unroll
    for (int o=16;o>0;o>>=1) v += __shfl_xor_sync(0xffffffffu, v, o);
    if ((d & 31) == 0) sh[d>>5] = v;
    __syncthreads();
    float var = (sh[0]+sh[1]+sh[2]+sh[3]) * (1.0f/128.0f);
    float y = c * rsqrtf(var + 1e-5f) * gam[d] + bet[d];
    int orow = row + (row>>11)*128;
    __nv_bfloat16 h = __float2bfloat16(y);
    oh[orow*128 + d] = h;
    ol[orow*128 + d] = __float2bfloat16(y - __bfloat162float(h));
}

__global__ void __launch_bounds__(256) k_memfill(const float* __restrict__ mem){
    int idx = blockIdx.x*256 + threadIdx.x;     // 8*128*128
    int b = idx >> 14, r = idx & 16383;
    float x = mem[r];
    __nv_bfloat16 h = __float2bfloat16(x);
    int o = (b*2176 + 2048)*128 + r;
    g_aqh[o] = h;
    g_aql[o] = __float2bfloat16(x - __bfloat162float(h));
}

__global__ void __launch_bounds__(128) k_buckets(const float* __restrict__ rot){
    __shared__ float srot[4352];
    int tid = threadIdx.x;
    for (int i = tid; i < 4352; i += 128) srot[i] = rot[i];
    __syncthreads();
    int bh = blockIdx.x, t = blockIdx.y*128 + tid;
    int b = bh / 6, head = 2 + bh % 6;
    const float* qp = g_qk + (((b<<3) + head)*2176 + t)*64;
    float rv[68];
#pragma unroll
    for (int u=0;u<68;u++) rv[u] = 0.0f;
    for (int f=0; f<64; f++){
        float qf = qp[f];
        const float* rp = &srot[f*68];
#pragma unroll
        for (int u=0;u<68;u++) rv[u] = fmaf(qf, rp[u], rv[u]);
    }
#pragma unroll
    for (int h=0; h<4; h++){
        float best = rv[h*17]; int bi = 0;
#pragma unroll
        for (int i=1;i<17;i++){ float v = rv[h*17+i]; if (v > best){ best = v; bi = i; } }
#pragma unroll
        for (int i=0;i<17;i++){ float v = -rv[h*17+i]; if (v > best){ best = v; bi = 17+i; } }
        g_bkt[bh*8704 + h*2176 + t] = bi + h*34;
    }
}

__global__ void __launch_bounds__(64) k_sort(){
    __shared__ int hist[64][136];
    __shared__ int base[136];
    int bh = blockIdx.x, t = threadIdx.x;
    int* hrow = hist[t];
    for (int i=0;i<136;i++) hrow[i] = 0;
    const int* bk = g_bkt + bh*8704;
    int i0 = t*136;
    for (int i=0;i<136;i++) hrow[bk[i0+i]]++;
    __syncthreads();
    for (int c = t; c < 136; c += 64){
        int run = 0;
        for (int tt=0; tt<64; tt++){ int v = hist[tt][c]; hist[tt][c] = run; run += v; }
        base[c] = run;
    }
    __syncthreads();
    if (t == 0){
        int run = 0;
        for (int c=0;c<136;c++){ int v = base[c]; base[c] = run; run += v; }
    }
    __syncthreads();
    for (int i=0;i<136;i++){
        int idx = i0 + i, bb = bk[idx];
        int pos = base[bb] + hrow[bb]; hrow[bb]++;
        g_st  [bh*8704 + pos] = idx % 2176;
        g_undo[bh*8704 + idx] = pos;
    }
}

// ---- LSH chunk attention: HMMA dots + PV ----
__global__ void __launch_bounds__(256) k_lsh_attn(){
    extern __shared__ char smc[];
    __nv_bfloat16* skb = (__nv_bfloat16*)smc;              // [128][72]
    __nv_bfloat16* svb = (__nv_bfloat16*)(smc + 18432);    // [128][72]
    float* sd          = (float*)(smc + 36864);            // [64][128]
    __nv_bfloat16* sp  = (__nv_bfloat16*)(smc + 69632);    // [64][136]
    float* scale       = (float*)(smc + 87040);            // [128]
    int*   skt         = (int*)(smc + 87552);              // [128]
    int bh = blockIdx.x, c = blockIdx.y, tid = threadIdx.x;
    int wid = tid >> 5, lane = tid & 31;
    int base  = bh*8704 + c*64;
    int pbase = bh*8704 + ((c + 135) % 136)*64;
    int b = bh / 6, head = 2 + bh % 6;
    int bhh = (b<<3) + head;
    for (int p = tid; p < 1024; p += 256){
        int row = p >> 3, c8 = p & 7;
        int src = (row < 64) ? g_st[base + row] : g_st[pbase + row - 64];
        const float4* qp = (const float4*)(g_qk + (bhh*2176 + src)*64 + c8*8);
        const float4* vp = (const float4*)(g_v  + (bhh*2176 + src)*64 + c8*8);
        *(uint4*)&skb[row*72 + c8*8] = f8_to_bf8(qp[0], qp[1]);
        *(uint4*)&svb[row*72 + c8*8] = f8_to_bf8(vp[0], vp[1]);
    }
    if (tid < 128)
        skt[tid] = (tid < 64) ? g_st[base + tid] : g_st[pbase + tid - 64];
    __syncthreads();
    if (tid < 128){
        float s = 0.f;
        const uint32_t* rp = (const uint32_t*)(skb + tid*72);
#pragma unroll
        for (int i = 0; i < 32; i++){
            float2 f = __bfloat1622float2(*(const __nv_bfloat162*)&rp[i]);
            s += f.x*f.x + f.y*f.y;
        }
        scale[tid] = 1.0f / fmaxf(sqrtf(s), 1e-12f);
    }
    __syncthreads();
    int wm = wid >> 1, wn = wid & 1;
    {
        float dacc[8][4] = {};
#pragma unroll
        for (int s = 0; s < 4; s++){
            uint32_t af[4];
            ldm4(af[0],af[1],af[2],af[3],
                 smem_u32(&skb[(wm*16 + (lane & 15))*72 + s*16 + (lane >> 4)*8]));
            uint32_t bf[8][2];
#pragma unroll
            for (int nt16 = 0; nt16 < 4; nt16++){
                int mi = lane >> 3;
                uint32_t r0,r1,r2,r3;
                ldm4(r0,r1,r2,r3,
                     smem_u32(&skb[(wn*64 + nt16*16 + (mi >> 1)*8 + (lane & 7))*72 + s*16 + (mi & 1)*8]));
                bf[nt16*2][0]   = r0; bf[nt16*2][1]   = r1;
                bf[nt16*2+1][0] = r2; bf[nt16*2+1][1] = r3;
            }
#pragma unroll
            for (int nt = 0; nt < 8; nt++)
                mma16816(dacc[nt], af, bf[nt]);
        }
#pragma unroll
        for (int nt = 0; nt < 8; nt++){
            int row = wm*16 + (lane >> 2);
            int col = wn*64 + nt*8 + (lane & 3)*2;
#pragma unroll
            for (int e = 0; e < 4; e++){
                int r = row + (e >> 1)*8, cc = col + (e & 1);
                int tq = skt[r], tk = skt[cc];
                float v = dacc[nt][e]*scale[cc]*0.125f;
                if (tq < tk)       v = -1e9f;
                else if (tq == tk) v = -5e4f;
                sd[r*128 + cc] = v;
            }
        }
    }
    __syncthreads();
    {
        int warp = wid, ln = lane;
        for (int rr=0; rr<8; rr++){
            int row = warp*8 + rr;
            float d0[4];
#pragma unroll
            for (int j=0;j<4;j++) d0[j] = sd[row*128 + ln + 32*j];
            float m = fmaxf(fmaxf(d0[0],d0[1]), fmaxf(d0[2],d0[3]));
#pragma unroll
            for (int o=16;o>0;o>>=1) m = fmaxf(m, __shfl_xor_sync(0xffffffffu, m, o));
            float p[4], s = 0.f;
#pragma unroll
            for (int j=0;j<4;j++){ p[j] = __expf(d0[j]-m); s += p[j]; }
#pragma unroll
            for (int o=16;o>0;o>>=1) s += __shfl_xor_sync(0xffffffffu, s, o);
            float inv = 1.0f/s;
#pragma unroll
            for (int j=0;j<4;j++) sp[row*136 + ln + 32*j] = __float2bfloat16(p[j]*inv);
            if (ln == 0) g_slog[base + row] = m + __logf(s);
        }
    }
    __syncthreads();
    {
        float pacc[4][4] = {};
#pragma unroll
        for (int s = 0; s < 8; s++){
            uint32_t af[4];
            ldm4(af[0],af[1],af[2],af[3],
                 smem_u32(&sp[(wm*16 + (lane & 15))*136 + s*16 + (lane >> 4)*8]));
            uint32_t bf[4][2];
#pragma unroll
            for (int nt16 = 0; nt16 < 2; nt16++){
                int mi = lane >> 3;
                uint32_t r0,r1,r2,r3;
                ldm4t(r0,r1,r2,r3,
                      smem_u32(&svb[(s*16 + (mi & 1)*8 + (lane & 7))*72 + wn*32 + nt16*16 + (mi >> 1)*8]));
                bf[nt16*2][0]   = r0; bf[nt16*2][1]   = r1;
                bf[nt16*2+1][0] = r2; bf[nt16*2+1][1] = r3;
            }
#pragma unroll
            for (int nt = 0; nt < 4; nt++)
                mma16816(pacc[nt], af, bf[nt]);
        }
#pragma unroll
        for (int nt = 0; nt < 4; nt++){
            int row = wm*16 + (lane >> 2);
            int col = wn*32 + nt*8 + (lane & 3)*2;
            g_so[(base + row)*64 + col]     = pacc[nt][0];
            g_so[(base + row)*64 + col + 1] = pacc[nt][1];
            g_so[(base + row + 8)*64 + col]     = pacc[nt][2];
            g_so[(base + row + 8)*64 + col + 1] = pacc[nt][3];
        }
    }
}

__global__ void __launch_bounds__(256) k_unsort(){
    int bh = blockIdx.y, tid = threadIdx.x;
    int g = tid >> 6, d = tid & 63;
    int t = blockIdx.x*4 + g;
    __shared__ int pos[4][4]; __shared__ float w[4][4];
    if (d < 4){
        int p = g_undo[bh*8704 + d*2176 + t];
        pos[g][d] = p; w[g][d] = g_slog[bh*8704 + p];
    }
    __syncthreads();
    if (d == 0){
        float m = fmaxf(fmaxf(w[g][0],w[g][1]), fmaxf(w[g][2],w[g][3]));
        float s = 0.f;
        for (int h=0;h<4;h++){ w[g][h] = __expf(w[g][h]-m); s += w[g][h]; }
        float inv = 1.0f/s;
        for (int h=0;h<4;h++) w[g][h] *= inv;
    }
    __syncthreads();
    float o = 0.f;
    for (int h=0;h<4;h++) o += w[g][h]*g_so[(bh*8704 + pos[g][h])*64 + d];
    int b = bh / 6, head = 2 + bh % 6;
    g_am[(b*2048 + t)*512 + head*64 + d] = __float2bfloat16(o);
}

// ---- local windowed attention: HMMA dots + PV, 64 q x 256 kv ----
__global__ void __launch_bounds__(256) k_local_attn(){
    extern __shared__ char smc[];
    __nv_bfloat16* skv = (__nv_bfloat16*)smc;              // [256][72]
    __nv_bfloat16* svb = (__nv_bfloat16*)(smc + 36864);    // [256][72]
    float* sd          = (float*)(smc + 73728);            // [64][256]
    __nv_bfloat16* sp  = (__nv_bfloat16*)(smc + 139264);   // [64][264]
    float* scale       = (float*)(smc + 173056);           // [256]
    int bh = blockIdx.x, b = bh >> 1, head = bh & 1;
    int win = blockIdx.y, half = blockIdx.z;
    int tid = threadIdx.x, wid = tid >> 5, lane = tid & 31;
    const float* qbase = g_qk + (((b<<3) + head)*2176)*64;
    const float* vbase = g_v  + (((b<<3) + head)*2176)*64;
    int q0 = win*128 + half*64;
    int qrow = 128 + half*64;
    for (int p = tid; p < 2048; p += 256){
        int row = p >> 3, c8 = p & 7;
        uint4 kv, vv;
        if (row < 128 && win == 0){
            kv = make_uint4(0,0,0,0); vv = kv;
        } else {
            int t = (row < 128) ? (win-1)*128 + row : win*128 + row - 128;
            const float4* qp = (const float4*)(qbase + t*64 + c8*8);
            const float4* vp = (const float4*)(vbase + t*64 + c8*8);
            kv = f8_to_bf8(qp[0], qp[1]);
            vv = f8_to_bf8(vp[0], vp[1]);
        }
        *(uint4*)&skv[row*72 + c8*8] = kv;
        *(uint4*)&svb[row*72 + c8*8] = vv;
    }
    __syncthreads();
    {
        float s = 0.f;
        const uint32_t* rp = (const uint32_t*)(skv + tid*72);
#pragma unroll
        for (int i = 0; i < 32; i++){
            float2 f = __bfloat1622float2(*(const __nv_bfloat162*)&rp[i]);
            s += f.x*f.x + f.y*f.y;
        }
        scale[tid] = 1.0f / fmaxf(sqrtf(s), 1e-12f);
    }
    __syncthreads();
    int wm = wid & 3, wn = wid >> 2;
    {
        float dacc[16][4] = {};
#pragma unroll
        for (int s = 0; s < 4; s++){
            uint32_t af[4];
            ldm4(af[0],af[1],af[2],af[3],
                 smem_u32(&skv[(qrow + wm*16 + (lane & 15))*72 + s*16 + (lane >> 4)*8]));
            uint32_t bf[16][2];
#pragma unroll
            for (int nt16 = 0; nt16 < 8; nt16++){
                int mi = lane >> 3;
                uint32_t r0,r1,r2,r3;
                ldm4(r0,r1,r2,r3,
                     smem_u32(&skv[(wn*128 + nt16*16 + (mi >> 1)*8 + (lane & 7))*72 + s*16 + (mi & 1)*8]));
                bf[nt16*2][0]   = r0; bf[nt16*2][1]   = r1;
                bf[nt16*2+1][0] = r2; bf[nt16*2+1][1] = r3;
            }
#pragma unroll
            for (int nt = 0; nt < 16; nt++)
                mma16816(dacc[nt], af, bf[nt]);
        }
#pragma unroll
        for (int nt = 0; nt < 16; nt++){
            int row = wm*16 + (lane >> 2);
            int col = wn*128 + nt*8 + (lane & 3)*2;
#pragma unroll
            for (int e = 0; e < 4; e++){
                int r = row + (e >> 1)*8, jc = col + (e & 1);
                int tq = q0 + r;
                float v = dacc[nt][e]*scale[jc]*0.125f;
                if (jc < 128){
                    if (win == 0) v = -1e9f;
                    else {
                        int tk = (win-1)*128 + jc;
                        if (tq == tk) v = -5e4f; else if (tq < tk) v = -1e9f;
                    }
                } else {
                    int tk = win*128 + jc - 128;
                    if (tq == tk) v = -5e4f; else if (tq < tk) v = -1e9f;
                }
                sd[r*256 + jc] = v;
            }
        }
    }
    __syncthreads();
    {
        int warp = wid, ln = lane;
        for (int rr=0; rr<8; rr++){
            int row = warp*8 + rr;
            float d0[8];
#pragma unroll
            for (int j=0;j<8;j++) d0[j] = sd[row*256 + ln + 32*j];
            float m = d0[0];
#pragma unroll
            for (int j=1;j<8;j++) m = fmaxf(m, d0[j]);
#pragma unroll
            for (int o=16;o>0;o>>=1) m = fmaxf(m, __shfl_xor_sync(0xffffffffu, m, o));
            float p[8], s = 0.f;
#pragma unroll
            for (int j=0;j<8;j++){ p[j] = __expf(d0[j]-m); s += p[j]; }
#pragma unroll
            for (int o=16;o>0;o>>=1) s += __shfl_xor_sync(0xffffffffu, s, o);
            float inv = 1.0f/s;
#pragma unroll
            for (int j=0;j<8;j++) sp[row*264 + ln + 32*j] = __float2bfloat16(p[j]*inv);
        }
    }
    __syncthreads();
    {
        int wm2 = wid & 3, wn2 = wid >> 2;
        float pacc[4][4] = {};
#pragma unroll
        for (int s = 0; s < 16; s++){
            uint32_t af[4];
            ldm4(af[0],af[1],af[2],af[3],
                 smem_u32(&sp[(wm2*16 + (lane & 15))*264 + s*16 + (lane >> 4)*8]));
            uint32_t bf[4][2];
#pragma unroll
            for (int nt16 = 0; nt16 < 2; nt16++){
                int mi = lane >> 3;
                uint32_t r0,r1,r2,r3;
                ldm4t(r0,r1,r2,r3,
                      smem_u32(&svb[(s*16 + (mi & 1)*8 + (lane & 7))*72 + wn2*32 + nt16*16 + (mi >> 1)*8]));
                bf[nt16*2][0]   = r0; bf[nt16*2][1]   = r1;
                bf[nt16*2+1][0] = r2; bf[nt16*2+1][1] = r3;
            }
#pragma unroll
            for (int nt = 0; nt < 4; nt++)
                mma16816(pacc[nt], af, bf[nt]);
        }
#pragma unroll
        for (int nt = 0; nt < 4; nt++){
            int row = wm2*16 + (lane >> 2);
            int col = wn2*32 + nt*8 + (lane & 3)*2;
#pragma unroll
            for (int e = 0; e < 4; e++){
                int r = row + (e >> 1)*8, cc = col + (e & 1);
                int t = q0 + r;
                if (t < 2048)
                    g_am[(b*2048 + t)*512 + head*64 + cc] = __float2bfloat16(pacc[nt][e]);
            }
        }
    }
}

__global__ void __launch_bounds__(128) k_pool(const float* __restrict__ in, float* __restrict__ out){
    int b = blockIdx.x >> 2, sub = blockIdx.x & 3, d = threadIdx.x;
    const float* p = in + (b*2048 + sub)*128 + d;
    float s = 0.f;
    for (int i=0;i<512;i++) s += p[i*512];
    out[b*512 + sub*128 + d] = s * (1.0f/512.0f);
}

extern "C" void kernel_launch(void* const* d_in, const int* in_sizes, int n_in,
                              void* d_out, int out_size){
    const float* features  = (const float*)d_in[0];
    const float* w_qk      = (const float*)d_in[1];
    const float* w_v       = (const float*)d_in[2];
    const float* mem_kv    = (const float*)d_in[3];
    const float* w_out     = (const float*)d_in[4];
    const float* b_out     = (const float*)d_in[5];
    const float* ln1_g     = (const float*)d_in[6];
    const float* ln1_b     = (const float*)d_in[7];
    const float* ff_w1     = (const float*)d_in[8];
    const float* ff_b1     = (const float*)d_in[9];
    const float* ff_w2     = (const float*)d_in[10];
    const float* ff_b2     = (const float*)d_in[11];
    const float* ln2_g     = (const float*)d_in[12];
    const float* ln2_b     = (const float*)d_in[13];
    const float* lnf_g     = (const float*)d_in[14];
    const float* lnf_b     = (const float*)d_in[15];
    const float* rotations = (const float*)d_in[16];
    float* out = (float*)d_out;

    float *x1,*x2,*fin,*qk,*vv;
    __nv_bfloat16 *aqh,*aql,*ain,*am,*ff,*wt_out,*wt_ff1,*wt_ff2;
    __nv_bfloat16 *wqk_h,*wqk_l,*wv_h,*wv_l;
    cudaGetSymbolAddress((void**)&x1,  g_x1);
    cudaGetSymbolAddress((void**)&x2,  g_x2);
    cudaGetSymbolAddress((void**)&fin, g_fin);
    cudaGetSymbolAddress((void**)&aqh, g_aqh);
    cudaGetSymbolAddress((void**)&aql, g_aql);
    cudaGetSymbolAddress((void**)&qk,  g_qk);
    cudaGetSymbolAddress((void**)&vv,  g_v);
    cudaGetSymbolAddress((void**)&ain, g_ain);
    cudaGetSymbolAddress((void**)&am,  g_am);
    cudaGetSymbolAddress((void**)&ff,  g_ff);
    cudaGetSymbolAddress((void**)&wt_out, g_wt_out);
    cudaGetSymbolAddress((void**)&wt_ff1, g_wt_ff1);
    cudaGetSymbolAddress((void**)&wt_ff2, g_wt_ff2);
    cudaGetSymbolAddress((void**)&wqk_h, g_wqk_h);
    cudaGetSymbolAddress((void**)&wqk_l, g_wqk_l);
    cudaGetSymbolAddress((void**)&wv_h,  g_wv_h);
    cudaGetSymbolAddress((void**)&wv_l,  g_wv_l);

    const int LSH_SMEM = 88064;
    const int LOC_SMEM = 174080;
    const int TG3_SMEM = 73728;
    cudaFuncSetAttribute(k_lsh_attn,   cudaFuncAttributeMaxDynamicSharedMemorySize, LSH_SMEM);
    cudaFuncSetAttribute(k_local_attn, cudaFuncAttributeMaxDynamicSharedMemorySize, LOC_SMEM);
    cudaFuncSetAttribute(k_tgemm3,     cudaFuncAttributeMaxDynamicSharedMemorySize, TG3_SMEM);

    for (int i = 0; i < 2; i++){
        k_wcvt<<<(128*512)/256,256>>>(w_out + i*512*128, wt_out + i*128*512, 512, 128);
        k_wcvt<<<(512*128)/256,256>>>(ff_w1 + i*128*512, wt_ff1 + i*512*128, 128, 512);
        k_wcvt<<<(128*512)/256,256>>>(ff_w2 + i*512*128, wt_ff2 + i*128*512, 512, 128);
        k_wcvt2<<<(512*128)/256,256>>>(w_qk + i*128*512, wqk_h + i*512*128, wqk_l + i*512*128, 128, 512);
        k_wcvt2<<<(512*128)/256,256>>>(w_v  + i*128*512, wv_h  + i*512*128, wv_l  + i*512*128, 128, 512);
    }

    k_embed<<<8192, 256>>>(features);

    for (int i = 0; i < 2; i++){
        k_ln_split<<<16384,128>>>(x2, aqh, aql, ln1_g + i*128, ln1_b + i*128);
        k_memfill<<<512,256>>>(mem_kv + i*128*128);
        EQKV eq; eq.out = qk;
        EQKV ev; ev.out = vv;
        k_tgemm3<<<dim3(4,136),256,TG3_SMEM>>>(aqh, aql, wqk_h + i*512*128, wqk_l + i*512*128, eq);
        k_tgemm3<<<dim3(4,136),256,TG3_SMEM>>>(aqh, aql, wv_h  + i*512*128, wv_l  + i*512*128, ev);
        k_local_attn<<<dim3(16,17,2),256,LOC_SMEM>>>();
        k_buckets<<<dim3(48,17),128>>>(rotations + i*64*4*17);
        k_sort<<<48,64>>>();
        k_lsh_attn<<<dim3(48,136),256,LSH_SMEM>>>();
        k_unsort<<<dim3(512,48),256>>>();
        EAddBias e1; e1.out = x1; e1.bias = b_out + i*128; e1.ld = 128;
        k_tgemm<<<dim3(1,128),256>>>(am, 512, wt_out + i*128*512, e1);
        k_layernorm<__nv_bfloat16><<<16384,128>>>(x1, (const float*)0, ain, ln2_g + i*128, ln2_b + i*128);
        EGelu eg; eg.out = ff; eg.bias = ff_b1 + i*512;
        k_tgemm<<<dim3(4,128),256>>>(ain, 128, wt_ff1 + i*512*128, eg);
        EAddBias e2; e2.out = x2; e2.bias = ff_b2 + i*128; e2.ld = 128;
        k_tgemm<<<dim3(1,128),256>>>(ff, 512, wt_ff2 + i*128*512, e2);
    }
    k_layernorm<float><<<16384,128>>>(x1, x2, fin, lnf_g, lnf_b);
    k_pool<<<32,128>>>(fin, out);
}

// round 15
// speedup vs baseline: 1.3326x; 1.3326x over previous
#include <cuda_runtime.h>
#include <cuda_bf16.h>
#include <math.h>
#include <stdint.h>

// B=8 S=512 FDIM=512 SUB=4 DIM=128 HEADS=8 DH=64 INNER=512
// T=2176 (2048+128 mem), NB=34, N_HASHES=4, BUCKET=64, C=136, 4T=8704

__device__ float g_x1 [8*2048*128];
__device__ float g_x2 [8*2048*128];
__device__ float g_fin[8*2048*128];
__device__ float g_aq [8*2176*128];              // fp32 qk GEMM input (feeds buckets!)
__device__ __nv_bfloat16 g_aqh[8*2176*128];      // bf16 copy for v GEMM
__device__ __nv_bfloat16 g_ain[8*2048*128];      // bf16 ff1 input
__device__ __nv_bfloat16 g_am [8*2048*512];      // bf16 merged attention output
__device__ __nv_bfloat16 g_ff [8*2048*512];      // bf16 gelu output
__device__ float g_qk [8*8*2176*64];
__device__ float g_v  [8*8*2176*64];
__device__ int   g_bkt [48*8704];
__device__ int   g_st  [48*8704];
__device__ int   g_undo[48*8704];
__device__ float g_so  [48*8704*64];
__device__ float g_slog[48*8704];
__device__ __nv_bfloat16 g_wt_out[2][128*512];   // w_out^T  [n=128][k=512]
__device__ __nv_bfloat16 g_wt_ff1[2][512*128];   // ff_w1^T  [n=512][k=128]
__device__ __nv_bfloat16 g_wt_ff2[2][128*512];   // ff_w2^T  [n=128][k=512]
__device__ __nv_bfloat16 g_wt_v  [2][512*128];   // w_v^T    [n=512][k=128]

__device__ __forceinline__ uint32_t smem_u32(const void* p){
    uint32_t a;
    asm("{ .reg .u64 t; cvta.to.shared.u64 t, %1; cvt.u32.u64 %0, t; }" : "=r"(a) : "l"(p));
    return a;
}
__device__ __forceinline__ void ldm4(uint32_t& r0, uint32_t& r1, uint32_t& r2, uint32_t& r3,
                                     uint32_t addr){
    asm volatile("ldmatrix.sync.aligned.m8n8.x4.shared.b16 {%0,%1,%2,%3}, [%4];"
        : "=r"(r0),"=r"(r1),"=r"(r2),"=r"(r3) : "r"(addr));
}
__device__ __forceinline__ void ldm4t(uint32_t& r0, uint32_t& r1, uint32_t& r2, uint32_t& r3,
                                      uint32_t addr){
    asm volatile("ldmatrix.sync.aligned.m8n8.x4.trans.shared.b16 {%0,%1,%2,%3}, [%4];"
        : "=r"(r0),"=r"(r1),"=r"(r2),"=r"(r3) : "r"(addr));
}
__device__ __forceinline__ void mma16816(float* c, const uint32_t* a, const uint32_t* b){
    asm volatile("mma.sync.aligned.m16n8k16.row.col.f32.bf16.bf16.f32 "
        "{%0,%1,%2,%3}, {%4,%5,%6,%7}, {%8,%9}, {%0,%1,%2,%3};"
        : "+f"(c[0]),"+f"(c[1]),"+f"(c[2]),"+f"(c[3])
        : "r"(a[0]),"r"(a[1]),"r"(a[2]),"r"(a[3]), "r"(b[0]),"r"(b[1]));
}
__device__ __forceinline__ uint4 f8_to_bf8(float4 a, float4 b){
    __nv_bfloat162 h0 = __floats2bfloat162_rn(a.x, a.y);
    __nv_bfloat162 h1 = __floats2bfloat162_rn(a.z, a.w);
    __nv_bfloat162 h2 = __floats2bfloat162_rn(b.x, b.y);
    __nv_bfloat162 h3 = __floats2bfloat162_rn(b.z, b.w);
    uint4 r;
    r.x = *(uint32_t*)&h0; r.y = *(uint32_t*)&h1;
    r.z = *(uint32_t*)&h2; r.w = *(uint32_t*)&h3;
    return r;
}

// ---- weight convert+transpose: fp32 [K][N] -> bf16 [N][K] ----
__global__ void __launch_bounds__(256) k_wcvt(const float* __restrict__ in,
                                              __nv_bfloat16* __restrict__ out,
                                              int K, int N){
    int idx = blockIdx.x*256 + threadIdx.x;
    int n = idx / K, k = idx - n*K;
    out[idx] = __float2bfloat16(in[k*N + n]);
}

// ====== HMMA GEMM: C[M,N] = A[M,K](bf16) * BT[N,K]^T, fp32 epilogue ======
struct EAddBias {
    float* out; const float* bias; int ld;
    __device__ __forceinline__ void operator()(int m, int n, float v) const {
        out[m*ld + n] += v + bias[n];
    }
};
struct EGelu {
    __nv_bfloat16* out; const float* bias;
    __device__ __forceinline__ void operator()(int m, int n, float v) const {
        float h = v + bias[n];
        out[m*512 + n] = __float2bfloat16(0.5f*h*(1.0f + erff(h*0.7071067811865475f)));
    }
};
struct EQKV {
    float* out;
    __device__ __forceinline__ void operator()(int m, int n, float v) const {
        int b = m / 2176, t = m - b*2176;
        out[(((b<<3) + (n>>6))*2176 + t)*64 + (n & 63)] = v;
    }
};

template<class EP>
__global__ void __launch_bounds__(256) k_tgemm(const __nv_bfloat16* __restrict__ A, int K,
                                               const __nv_bfloat16* __restrict__ BT,
                                               EP ep){
    __shared__ __nv_bfloat16 As[128][72];
    __shared__ __nv_bfloat16 Bs[128][72];
    int tid = threadIdx.x, wid = tid >> 5, lane = tid & 31;
    int wm = wid >> 1, wn = wid & 1;
    int bm = blockIdx.y*128, bn = blockIdx.x*128;
    float acc[2][8][4] = {};
    int nc = K >> 6;
    for (int kc = 0; kc < nc; kc++){
        for (int p = tid; p < 1024; p += 256){
            int row = p >> 3, q = p & 7;
            *(uint4*)&As[row][q*8] = *(const uint4*)(A  + (size_t)(bm+row)*K + kc*64 + q*8);
            *(uint4*)&Bs[row][q*8] = *(const uint4*)(BT + (size_t)(bn+row)*K + kc*64 + q*8);
        }
        __syncthreads();
#pragma unroll
        for (int s = 0; s < 4; s++){
            uint32_t af[2][4];
#pragma unroll
            for (int mt = 0; mt < 2; mt++){
                uint32_t addr = smem_u32(&As[wm*32 + mt*16 + (lane & 15)][s*16 + (lane >> 4)*8]);
                ldm4(af[mt][0], af[mt][1], af[mt][2], af[mt][3], addr);
            }
            uint32_t bf[8][2];
#pragma unroll
            for (int nt16 = 0; nt16 < 4; nt16++){
                int mi = lane >> 3;
                uint32_t addr = smem_u32(&Bs[wn*64 + nt16*16 + (mi >> 1)*8 + (lane & 7)][s*16 + (mi & 1)*8]);
                uint32_t r0,r1,r2,r3;
                ldm4(r0,r1,r2,r3, addr);
                bf[nt16*2][0]   = r0; bf[nt16*2][1]   = r1;
                bf[nt16*2+1][0] = r2; bf[nt16*2+1][1] = r3;
            }
#pragma unroll
            for (int mt = 0; mt < 2; mt++)
#pragma unroll
                for (int nt = 0; nt < 8; nt++)
                    mma16816(acc[mt][nt], af[mt], bf[nt]);
        }
        __syncthreads();
    }
#pragma unroll
    for (int mt = 0; mt < 2; mt++){
#pragma unroll
        for (int nt = 0; nt < 8; nt++){
            int m = bm + wm*32 + mt*16 + (lane >> 2);
            int n = bn + wn*64 + nt*8 + (lane & 3)*2;
            ep(m,   n,   acc[mt][nt][0]);
            ep(m,   n+1, acc[mt][nt][1]);
            ep(m+8, n,   acc[mt][nt][2]);
            ep(m+8, n+1, acc[mt][nt][3]);
        }
    }
}

// ================= rest of pipeline =================
__global__ void __launch_bounds__(256) k_embed(const float* __restrict__ feat){
    int idx = blockIdx.x*256 + threadIdx.x;
    int b = idx >> 18, r = idx & 262143;
    int t = r >> 7, d = r & 127;
    int s = t >> 2, f = ((t & 3) << 7) + d;
    float inv = expf(-(2.0f*(float)f/512.0f)*9.210340371976184f);
    float ang = (float)s * inv;
    float pe = (f & 1) ? cosf(ang) : sinf(ang);
    float v = feat[(b*512 + s)*512 + f] + pe;
    g_x1[idx] = v; g_x2[idx] = v;
}

template<typename OutT>
__global__ void __launch_bounds__(128) k_layernorm(const float* __restrict__ in1,
                                                   const float* __restrict__ in2,
                                                   OutT* __restrict__ outp,
                                                   const float* __restrict__ gam,
                                                   const float* __restrict__ bet){
    int row = blockIdx.x, d = threadIdx.x;
    float x = in1[row*128 + d];
    if (in2) x = 0.5f*(x + in2[row*128 + d]);
    __shared__ float sh[4];
    float s = x;
#pragma unroll
    for (int o=16;o>0;o>>=1) s += __shfl_xor_sync(0xffffffffu, s, o);
    if ((d & 31) == 0) sh[d>>5] = s;
    __syncthreads();
    float mean = (sh[0]+sh[1]+sh[2]+sh[3]) * (1.0f/128.0f);
    float c = x - mean;
    __syncthreads();
    float v = c*c;
#pragma unroll
    for (int o=16;o>0;o>>=1) v += __shfl_xor_sync(0xffffffffu, v, o);
    if ((d & 31) == 0) sh[d>>5] = v;
    __syncthreads();
    float var = (sh[0]+sh[1]+sh[2]+sh[3]) * (1.0f/128.0f);
    outp[row*128 + d] = (OutT)(c * rsqrtf(var + 1e-5f) * gam[d] + bet[d]);
}

// LN -> packed fp32 + bf16 (rows b*2048+t -> b*2176+t)
__global__ void __launch_bounds__(128) k_ln_qkv(const float* __restrict__ in1,
                                                const float* __restrict__ gam,
                                                const float* __restrict__ bet){
    int row = blockIdx.x, d = threadIdx.x;
    float x = in1[row*128 + d];
    __shared__ float sh[4];
    float s = x;
#pragma unroll
    for (int o=16;o>0;o>>=1) s += __shfl_xor_sync(0xffffffffu, s, o);
    if ((d & 31) == 0) sh[d>>5] = s;
    __syncthreads();
    float mean = (sh[0]+sh[1]+sh[2]+sh[3]) * (1.0f/128.0f);
    float c = x - mean;
    __syncthreads();
    float v = c*c;
#pragma unroll
    for (int o=16;o>0;o>>=1) v += __shfl_xor_sync(0xffffffffu, v, o);
    if ((d & 31) == 0) sh[d>>5] = v;
    __syncthreads();
    float var = (sh[0]+sh[1]+sh[2]+sh[3]) * (1.0f/128.0f);
    float y = c * rsqrtf(var + 1e-5f) * gam[d] + bet[d];
    int orow = row + (row>>11)*128;
    g_aq [orow*128 + d] = y;
    g_aqh[orow*128 + d] = __float2bfloat16(y);
}

__global__ void __launch_bounds__(256) k_memfill(const float* __restrict__ mem){
    int idx = blockIdx.x*256 + threadIdx.x;     // 8*128*128
    int b = idx >> 14, r = idx & 16383;
    float x = mem[r];
    int o = (b*2176 + 2048)*128 + r;
    g_aq [o] = x;
    g_aqh[o] = __float2bfloat16(x);
}

// fp32 GEMM (qk only — feeds LSH argmax, must stay fp32)
template<class EP>
__global__ void __launch_bounds__(256) k_gemm(const float* __restrict__ A, int K,
                                              const float* __restrict__ Bm, int N,
                                              EP ep){
    __shared__ float As[2][16][132];
    __shared__ float Bs[2][16][132];
    int bm = blockIdx.y*128, bn = blockIdx.x*128;
    int tid = threadIdx.x, tx = tid & 15, ty = tid >> 4;
    int arow = tid >> 1, aq = tid & 1;
    int bkk = tid >> 4, bv = tid & 15;
    float acc[8][8] = {};
    const float* Arow = A + (bm+arow)*K;
    {
        float4 a0 = *(const float4*)(Arow + aq*4);
        float4 a1 = *(const float4*)(Arow + (aq+2)*4);
        float4 b0 = *(const float4*)(Bm + bkk*N + bn + bv*4);
        float4 b1 = *(const float4*)(Bm + bkk*N + bn + bv*4 + 64);
        As[0][aq*4+0][arow] = a0.x; As[0][aq*4+1][arow] = a0.y;
        As[0][aq*4+2][arow] = a0.z; As[0][aq*4+3][arow] = a0.w;
        As[0][aq*4+8][arow] = a1.x; As[0][aq*4+9][arow] = a1.y;
        As[0][aq*4+10][arow] = a1.z; As[0][aq*4+11][arow] = a1.w;
        *(float4*)&Bs[0][bkk][bv*4]      = b0;
        *(float4*)&Bs[0][bkk][bv*4 + 64] = b1;
    }
    __syncthreads();
    int nt = K >> 4;
    for (int t = 0; t < nt; t++){
        int cur = t & 1, nxt = cur ^ 1;
        float4 na0, na1, nb0, nb1;
        if (t+1 < nt){
            int k0 = (t+1) << 4;
            na0 = *(const float4*)(Arow + k0 + aq*4);
            na1 = *(const float4*)(Arow + k0 + (aq+2)*4);
            nb0 = *(const float4*)(Bm + (k0+bkk)*N + bn + bv*4);
            nb1 = *(const float4*)(Bm + (k0+bkk)*N + bn + bv*4 + 64);
        }
#pragma unroll
        for (int kk=0;kk<16;kk++){
            float4 a0 = *(float4*)&As[cur][kk][ty*8];
            float4 a1 = *(float4*)&As[cur][kk][ty*8+4];
            float4 b0 = *(float4*)&Bs[cur][kk][tx*8];
            float4 b1 = *(float4*)&Bs[cur][kk][tx*8+4];
            float av[8] = {a0.x,a0.y,a0.z,a0.w,a1.x,a1.y,a1.z,a1.w};
            float bv2[8] = {b0.x,b0.y,b0.z,b0.w,b1.x,b1.y,b1.z,b1.w};
#pragma unroll
            for (int i=0;i<8;i++)
#pragma unroll
                for (int j=0;j<8;j++) acc[i][j] = fmaf(av[i], bv2[j], acc[i][j]);
        }
        if (t+1 < nt){
            As[nxt][aq*4+0][arow] = na0.x; As[nxt][aq*4+1][arow] = na0.y;
            As[nxt][aq*4+2][arow] = na0.z; As[nxt][aq*4+3][arow] = na0.w;
            As[nxt][aq*4+8][arow] = na1.x; As[nxt][aq*4+9][arow] = na1.y;
            As[nxt][aq*4+10][arow] = na1.z; As[nxt][aq*4+11][arow] = na1.w;
            *(float4*)&Bs[nxt][bkk][bv*4]      = nb0;
            *(float4*)&Bs[nxt][bkk][bv*4 + 64] = nb1;
            __syncthreads();
        }
    }
#pragma unroll
    for (int i=0;i<8;i++)
#pragma unroll
        for (int j=0;j<8;j++) ep(bm + ty*8 + i, bn + tx*8 + j, acc[i][j]);
}

__global__ void __launch_bounds__(128) k_buckets(const float* __restrict__ rot){
    __shared__ float srot[4352];
    int tid = threadIdx.x;
    for (int i = tid; i < 4352; i += 128) srot[i] = rot[i];
    __syncthreads();
    int bh = blockIdx.x, t = blockIdx.y*128 + tid;
    int b = bh / 6, head = 2 + bh % 6;
    const float* qp = g_qk + (((b<<3) + head)*2176 + t)*64;
    float rv[68];
#pragma unroll
    for (int u=0;u<68;u++) rv[u] = 0.0f;
    for (int f=0; f<64; f++){
        float qf = qp[f];
        const float* rp = &srot[f*68];
#pragma unroll
        for (int u=0;u<68;u++) rv[u] = fmaf(qf, rp[u], rv[u]);
    }
#pragma unroll
    for (int h=0; h<4; h++){
        float best = rv[h*17]; int bi = 0;
#pragma unroll
        for (int i=1;i<17;i++){ float v = rv[h*17+i]; if (v > best){ best = v; bi = i; } }
#pragma unroll
        for (int i=0;i<17;i++){ float v = -rv[h*17+i]; if (v > best){ best = v; bi = 17+i; } }
        g_bkt[bh*8704 + h*2176 + t] = bi + h*34;
    }
}

__global__ void __launch_bounds__(64) k_sort(){
    __shared__ int hist[64][136];
    __shared__ int base[136];
    int bh = blockIdx.x, t = threadIdx.x;
    int* hrow = hist[t];
    for (int i=0;i<136;i++) hrow[i] = 0;
    const int* bk = g_bkt + bh*8704;
    int i0 = t*136;
    for (int i=0;i<136;i++) hrow[bk[i0+i]]++;
    __syncthreads();
    for (int c = t; c < 136; c += 64){
        int run = 0;
        for (int tt=0; tt<64; tt++){ int v = hist[tt][c]; hist[tt][c] = run; run += v; }
        base[c] = run;
    }
    __syncthreads();
    if (t == 0){
        int run = 0;
        for (int c=0;c<136;c++){ int v = base[c]; base[c] = run; run += v; }
    }
    __syncthreads();
    for (int i=0;i<136;i++){
        int idx = i0 + i, bb = bk[idx];
        int pos = base[bb] + hrow[bb]; hrow[bb]++;
        g_st  [bh*8704 + pos] = idx % 2176;
        g_undo[bh*8704 + idx] = pos;
    }
}

// ---- LSH chunk attention: HMMA dots + PV ----
__global__ void __launch_bounds__(256) k_lsh_attn(){
    extern __shared__ char smc[];
    __nv_bfloat16* skb = (__nv_bfloat16*)smc;              // [128][72]
    __nv_bfloat16* svb = (__nv_bfloat16*)(smc + 18432);    // [128][72]
    float* sd          = (float*)(smc + 36864);            // [64][128]
    __nv_bfloat16* sp  = (__nv_bfloat16*)(smc + 69632);    // [64][136]
    float* scale       = (float*)(smc + 87040);            // [128]
    int*   skt         = (int*)(smc + 87552);              // [128]
    int bh = blockIdx.x, c = blockIdx.y, tid = threadIdx.x;
    int wid = tid >> 5, lane = tid & 31;
    int base  = bh*8704 + c*64;
    int pbase = bh*8704 + ((c + 135) % 136)*64;
    int b = bh / 6, head = 2 + bh % 6;
    int bhh = (b<<3) + head;
    for (int p = tid; p < 1024; p += 256){
        int row = p >> 3, c8 = p & 7;
        int src = (row < 64) ? g_st[base + row] : g_st[pbase + row - 64];
        const float4* qp = (const float4*)(g_qk + (bhh*2176 + src)*64 + c8*8);
        const float4* vp = (const float4*)(g_v  + (bhh*2176 + src)*64 + c8*8);
        *(uint4*)&skb[row*72 + c8*8] = f8_to_bf8(qp[0], qp[1]);
        *(uint4*)&svb[row*72 + c8*8] = f8_to_bf8(vp[0], vp[1]);
    }
    if (tid < 128)
        skt[tid] = (tid < 64) ? g_st[base + tid] : g_st[pbase + tid - 64];
    __syncthreads();
    if (tid < 128){
        float s = 0.f;
        const uint32_t* rp = (const uint32_t*)(skb + tid*72);
#pragma unroll
        for (int i = 0; i < 32; i++){
            float2 f = __bfloat1622float2(*(const __nv_bfloat162*)&rp[i]);
            s += f.x*f.x + f.y*f.y;
        }
        scale[tid] = 1.0f / fmaxf(sqrtf(s), 1e-12f);
    }
    __syncthreads();
    int wm = wid >> 1, wn = wid & 1;
    {
        float dacc[8][4] = {};
#pragma unroll
        for (int s = 0; s < 4; s++){
            uint32_t af[4];
            ldm4(af[0],af[1],af[2],af[3],
                 smem_u32(&skb[(wm*16 + (lane & 15))*72 + s*16 + (lane >> 4)*8]));
            uint32_t bf[8][2];
#pragma unroll
            for (int nt16 = 0; nt16 < 4; nt16++){
                int mi = lane >> 3;
                uint32_t r0,r1,r2,r3;
                ldm4(r0,r1,r2,r3,
                     smem_u32(&skb[(wn*64 + nt16*16 + (mi >> 1)*8 + (lane & 7))*72 + s*16 + (mi & 1)*8]));
                bf[nt16*2][0]   = r0; bf[nt16*2][1]   = r1;
                bf[nt16*2+1][0] = r2; bf[nt16*2+1][1] = r3;
            }
#pragma unroll
            for (int nt = 0; nt < 8; nt++)
                mma16816(dacc[nt], af, bf[nt]);
        }
#pragma unroll
        for (int nt = 0; nt < 8; nt++){
            int row = wm*16 + (lane >> 2);
            int col = wn*64 + nt*8 + (lane & 3)*2;
#pragma unroll
            for (int e = 0; e < 4; e++){
                int r = row + (e >> 1)*8, cc = col + (e & 1);
                int tq = skt[r], tk = skt[cc];
                float v = dacc[nt][e]*scale[cc]*0.125f;
                if (tq < tk)       v = -1e9f;
                else if (tq == tk) v = -5e4f;
                sd[r*128 + cc] = v;
            }
        }
    }
    __syncthreads();
    {
        int warp = wid, ln = lane;
        for (int rr=0; rr<8; rr++){
            int row = warp*8 + rr;
            float d0[4];
#pragma unroll
            for (int j=0;j<4;j++) d0[j] = sd[row*128 + ln + 32*j];
            float m = fmaxf(fmaxf(d0[0],d0[1]), fmaxf(d0[2],d0[3]));
#pragma unroll
            for (int o=16;o>0;o>>=1) m = fmaxf(m, __shfl_xor_sync(0xffffffffu, m, o));
            float p[4], s = 0.f;
#pragma unroll
            for (int j=0;j<4;j++){ p[j] = __expf(d0[j]-m); s += p[j]; }
#pragma unroll
            for (int o=16;o>0;o>>=1) s += __shfl_xor_sync(0xffffffffu, s, o);
            float inv = 1.0f/s;
#pragma unroll
            for (int j=0;j<4;j++) sp[row*136 + ln + 32*j] = __float2bfloat16(p[j]*inv);
            if (ln == 0) g_slog[base + row] = m + __logf(s);
        }
    }
    __syncthreads();
    {
        float pacc[4][4] = {};
#pragma unroll
        for (int s = 0; s < 8; s++){
            uint32_t af[4];
            ldm4(af[0],af[1],af[2],af[3],
                 smem_u32(&sp[(wm*16 + (lane & 15))*136 + s*16 + (lane >> 4)*8]));
            uint32_t bf[4][2];
#pragma unroll
            for (int nt16 = 0; nt16 < 2; nt16++){
                int mi = lane >> 3;
                uint32_t r0,r1,r2,r3;
                ldm4t(r0,r1,r2,r3,
                      smem_u32(&svb[(s*16 + (mi & 1)*8 + (lane & 7))*72 + wn*32 + nt16*16 + (mi >> 1)*8]));
                bf[nt16*2][0]   = r0; bf[nt16*2][1]   = r1;
                bf[nt16*2+1][0] = r2; bf[nt16*2+1][1] = r3;
            }
#pragma unroll
            for (int nt = 0; nt < 4; nt++)
                mma16816(pacc[nt], af, bf[nt]);
        }
#pragma unroll
        for (int nt = 0; nt < 4; nt++){
            int row = wm*16 + (lane >> 2);
            int col = wn*32 + nt*8 + (lane & 3)*2;
            g_so[(base + row)*64 + col]     = pacc[nt][0];
            g_so[(base + row)*64 + col + 1] = pacc[nt][1];
            g_so[(base + row + 8)*64 + col]     = pacc[nt][2];
            g_so[(base + row + 8)*64 + col + 1] = pacc[nt][3];
        }
    }
}

__global__ void __launch_bounds__(256) k_unsort(){
    int bh = blockIdx.y, tid = threadIdx.x;
    int g = tid >> 6, d = tid & 63;
    int t = blockIdx.x*4 + g;
    __shared__ int pos[4][4]; __shared__ float w[4][4];
    if (d < 4){
        int p = g_undo[bh*8704 + d*2176 + t];
        pos[g][d] = p; w[g][d] = g_slog[bh*8704 + p];
    }
    __syncthreads();
    if (d == 0){
        float m = fmaxf(fmaxf(w[g][0],w[g][1]), fmaxf(w[g][2],w[g][3]));
        float s = 0.f;
        for (int h=0;h<4;h++){ w[g][h] = __expf(w[g][h]-m); s += w[g][h]; }
        float inv = 1.0f/s;
        for (int h=0;h<4;h++) w[g][h] *= inv;
    }
    __syncthreads();
    float o = 0.f;
    for (int h=0;h<4;h++) o += w[g][h]*g_so[(bh*8704 + pos[g][h])*64 + d];
    int b = bh / 6, head = 2 + bh % 6;
    g_am[(b*2048 + t)*512 + head*64 + d] = __float2bfloat16(o);
}

// ---- local windowed attention: HMMA dots + PV, 64 q x 256 kv ----
__global__ void __launch_bounds__(256) k_local_attn(){
    extern __shared__ char smc[];
    __nv_bfloat16* skv = (__nv_bfloat16*)smc;              // [256][72]
    __nv_bfloat16* svb = (__nv_bfloat16*)(smc + 36864);    // [256][72]
    float* sd          = (float*)(smc + 73728);            // [64][256]
    __nv_bfloat16* sp  = (__nv_bfloat16*)(smc + 139264);   // [64][264]
    float* scale       = (float*)(smc + 173056);           // [256]
    int bh = blockIdx.x, b = bh >> 1, head = bh & 1;
    int win = blockIdx.y, half = blockIdx.z;
    int tid = threadIdx.x, wid = tid >> 5, lane = tid & 31;
    const float* qbase = g_qk + (((b<<3) + head)*2176)*64;
    const float* vbase = g_v  + (((b<<3) + head)*2176)*64;
    int q0 = win*128 + half*64;
    int qrow = 128 + half*64;
    for (int p = tid; p < 2048; p += 256){
        int row = p >> 3, c8 = p & 7;
        uint4 kv, vv;
        if (row < 128 && win == 0){
            kv = make_uint4(0,0,0,0); vv = kv;
        } else {
            int t = (row < 128) ? (win-1)*128 + row : win*128 + row - 128;
            const float4* qp = (const float4*)(qbase + t*64 + c8*8);
            const float4* vp = (const float4*)(vbase + t*64 + c8*8);
            kv = f8_to_bf8(qp[0], qp[1]);
            vv = f8_to_bf8(vp[0], vp[1]);
        }
        *(uint4*)&skv[row*72 + c8*8] = kv;
        *(uint4*)&svb[row*72 + c8*8] = vv;
    }
    __syncthreads();
    {
        float s = 0.f;
        const uint32_t* rp = (const uint32_t*)(skv + tid*72);
#pragma unroll
        for (int i = 0; i < 32; i++){
            float2 f = __bfloat1622float2(*(const __nv_bfloat162*)&rp[i]);
            s += f.x*f.x + f.y*f.y;
        }
        scale[tid] = 1.0f / fmaxf(sqrtf(s), 1e-12f);
    }
    __syncthreads();
    int wm = wid & 3, wn = wid >> 2;
    {
        float dacc[16][4] = {};
#pragma unroll
        for (int s = 0; s < 4; s++){
            uint32_t af[4];
            ldm4(af[0],af[1],af[2],af[3],
                 smem_u32(&skv[(qrow + wm*16 + (lane & 15))*72 + s*16 + (lane >> 4)*8]));
            uint32_t bf[16][2];
#pragma unroll
            for (int nt16 = 0; nt16 < 8; nt16++){
                int mi = lane >> 3;
                uint32_t r0,r1,r2,r3;
                ldm4(r0,r1,r2,r3,
                     smem_u32(&skv[(wn*128 + nt16*16 + (mi >> 1)*8 + (lane & 7))*72 + s*16 + (mi & 1)*8]));
                bf[nt16*2][0]   = r0; bf[nt16*2][1]   = r1;
                bf[nt16*2+1][0] = r2; bf[nt16*2+1][1] = r3;
            }
#pragma unroll
            for (int nt = 0; nt < 16; nt++)
                mma16816(dacc[nt], af, bf[nt]);
        }
#pragma unroll
        for (int nt = 0; nt < 16; nt++){
            int row = wm*16 + (lane >> 2);
            int col = wn*128 + nt*8 + (lane & 3)*2;
#pragma unroll
            for (int e = 0; e < 4; e++){
                int r = row + (e >> 1)*8, jc = col + (e & 1);
                int tq = q0 + r;
                float v = dacc[nt][e]*scale[jc]*0.125f;
                if (jc < 128){
                    if (win == 0) v = -1e9f;
                    else {
                        int tk = (win-1)*128 + jc;
                        if (tq == tk) v = -5e4f; else if (tq < tk) v = -1e9f;
                    }
                } else {
                    int tk = win*128 + jc - 128;
                    if (tq == tk) v = -5e4f; else if (tq < tk) v = -1e9f;
                }
                sd[r*256 + jc] = v;
            }
        }
    }
    __syncthreads();
    {
        int warp = wid, ln = lane;
        for (int rr=0; rr<8; rr++){
            int row = warp*8 + rr;
            float d0[8];
#pragma unroll
            for (int j=0;j<8;j++) d0[j] = sd[row*256 + ln + 32*j];
            float m = d0[0];
#pragma unroll
            for (int j=1;j<8;j++) m = fmaxf(m, d0[j]);
#pragma unroll
            for (int o=16;o>0;o>>=1) m = fmaxf(m, __shfl_xor_sync(0xffffffffu, m, o));
            float p[8], s = 0.f;
#pragma unroll
            for (int j=0;j<8;j++){ p[j] = __expf(d0[j]-m); s += p[j]; }
#pragma unroll
            for (int o=16;o>0;o>>=1) s += __shfl_xor_sync(0xffffffffu, s, o);
            float inv = 1.0f/s;
#pragma unroll
            for (int j=0;j<8;j++) sp[row*264 + ln + 32*j] = __float2bfloat16(p[j]*inv);
        }
    }
    __syncthreads();
    {
        int wm2 = wid & 3, wn2 = wid >> 2;
        float pacc[4][4] = {};
#pragma unroll
        for (int s = 0; s < 16; s++){
            uint32_t af[4];
            ldm4(af[0],af[1],af[2],af[3],
                 smem_u32(&sp[(wm2*16 + (lane & 15))*264 + s*16 + (lane >> 4)*8]));
            uint32_t bf[4][2];
#pragma unroll
            for (int nt16 = 0; nt16 < 2; nt16++){
                int mi = lane >> 3;
                uint32_t r0,r1,r2,r3;
                ldm4t(r0,r1,r2,r3,
                      smem_u32(&svb[(s*16 + (mi & 1)*8 + (lane & 7))*72 + wn2*32 + nt16*16 + (mi >> 1)*8]));
                bf[nt16*2][0]   = r0; bf[nt16*2][1]   = r1;
                bf[nt16*2+1][0] = r2; bf[nt16*2+1][1] = r3;
            }
#pragma unroll
            for (int nt = 0; nt < 4; nt++)
                mma16816(pacc[nt], af, bf[nt]);
        }
#pragma unroll
        for (int nt = 0; nt < 4; nt++){
            int row = wm2*16 + (lane >> 2);
            int col = wn2*32 + nt*8 + (lane & 3)*2;
#pragma unroll
            for (int e = 0; e < 4; e++){
                int r = row + (e >> 1)*8, cc = col + (e & 1);
                int t = q0 + r;
                if (t < 2048)
                    g_am[(b*2048 + t)*512 + head*64 + cc] = __float2bfloat16(pacc[nt][e]);
            }
        }
    }
}

__global__ void __launch_bounds__(128) k_pool(const float* __restrict__ in, float* __restrict__ out){
    int b = blockIdx.x >> 2, sub = blockIdx.x & 3, d = threadIdx.x;
    const float* p = in + (b*2048 + sub)*128 + d;
    float s = 0.f;
    for (int i=0;i<512;i++) s += p[i*512];
    out[b*512 + sub*128 + d] = s * (1.0f/512.0f);
}

extern "C" void kernel_launch(void* const* d_in, const int* in_sizes, int n_in,
                              void* d_out, int out_size){
    const float* features  = (const float*)d_in[0];
    const float* w_qk      = (const float*)d_in[1];
    const float* w_v       = (const float*)d_in[2];
    const float* mem_kv    = (const float*)d_in[3];
    const float* w_out     = (const float*)d_in[4];
    const float* b_out     = (const float*)d_in[5];
    const float* ln1_g     = (const float*)d_in[6];
    const float* ln1_b     = (const float*)d_in[7];
    const float* ff_w1     = (const float*)d_in[8];
    const float* ff_b1     = (const float*)d_in[9];
    const float* ff_w2     = (const float*)d_in[10];
    const float* ff_b2     = (const float*)d_in[11];
    const float* ln2_g     = (const float*)d_in[12];
    const float* ln2_b     = (const float*)d_in[13];
    const float* lnf_g     = (const float*)d_in[14];
    const float* lnf_b     = (const float*)d_in[15];
    const float* rotations = (const float*)d_in[16];
    float* out = (float*)d_out;

    float *x1,*x2,*fin,*aq,*qk,*vv;
    __nv_bfloat16 *aqh,*ain,*am,*ff,*wt_out,*wt_ff1,*wt_ff2,*wt_v;
    cudaGetSymbolAddress((void**)&x1,  g_x1);
    cudaGetSymbolAddress((void**)&x2,  g_x2);
    cudaGetSymbolAddress((void**)&fin, g_fin);
    cudaGetSymbolAddress((void**)&aq,  g_aq);
    cudaGetSymbolAddress((void**)&aqh, g_aqh);
    cudaGetSymbolAddress((void**)&qk,  g_qk);
    cudaGetSymbolAddress((void**)&vv,  g_v);
    cudaGetSymbolAddress((void**)&ain, g_ain);
    cudaGetSymbolAddress((void**)&am,  g_am);
    cudaGetSymbolAddress((void**)&ff,  g_ff);
    cudaGetSymbolAddress((void**)&wt_out, g_wt_out);
    cudaGetSymbolAddress((void**)&wt_ff1, g_wt_ff1);
    cudaGetSymbolAddress((void**)&wt_ff2, g_wt_ff2);
    cudaGetSymbolAddress((void**)&wt_v,   g_wt_v);

    const int LSH_SMEM = 88064;
    const int LOC_SMEM = 174080;
    cudaFuncSetAttribute(k_lsh_attn,   cudaFuncAttributeMaxDynamicSharedMemorySize, LSH_SMEM);
    cudaFuncSetAttribute(k_local_attn, cudaFuncAttributeMaxDynamicSharedMemorySize, LOC_SMEM);

    for (int i = 0; i < 2; i++){
        k_wcvt<<<(128*512)/256,256>>>(w_out + i*512*128, wt_out + i*128*512, 512, 128);
        k_wcvt<<<(512*128)/256,256>>>(ff_w1 + i*128*512, wt_ff1 + i*512*128, 128, 512);
        k_wcvt<<<(128*512)/256,256>>>(ff_w2 + i*512*128, wt_ff2 + i*128*512, 512, 128);
        k_wcvt<<<(512*128)/256,256>>>(w_v   + i*128*512, wt_v   + i*512*128, 128, 512);
    }

    k_embed<<<8192, 256>>>(features);

    for (int i = 0; i < 2; i++){
        k_ln_qkv<<<16384,128>>>(x2, ln1_g + i*128, ln1_b + i*128);
        k_memfill<<<512,256>>>(mem_kv + i*128*128);
        EQKV eq; eq.out = qk;
        EQKV ev; ev.out = vv;
        // qk: fp32 (feeds argmax); v: bf16 tensor-core
        k_gemm<<<dim3(4,136),256>>>(aq, 128, w_qk + i*128*512, 512, eq);
        k_tgemm<<<dim3(4,136),256>>>(aqh, 128, wt_v + i*512*128, ev);
        k_local_attn<<<dim3(16,17,2),256,LOC_SMEM>>>();
        k_buckets<<<dim3(48,17),128>>>(rotations + i*64*4*17);
        k_sort<<<48,64>>>();
        k_lsh_attn<<<dim3(48,136),256,LSH_SMEM>>>();
        k_unsort<<<dim3(512,48),256>>>();
        EAddBias e1; e1.out = x1; e1.bias = b_out + i*128; e1.ld = 128;
        k_tgemm<<<dim3(1,128),256>>>(am, 512, wt_out + i*128*512, e1);
        k_layernorm<__nv_bfloat16><<<16384,128>>>(x1, (const float*)0, ain, ln2_g + i*128, ln2_b + i*128);
        EGelu eg; eg.out = ff; eg.bias = ff_b1 + i*512;
        k_tgemm<<<dim3(4,128),256>>>(ain, 128, wt_ff1 + i*512*128, eg);
        EAddBias e2; e2.out = x2; e2.bias = ff_b2 + i*128; e2.ld = 128;
        k_tgemm<<<dim3(1,128),256>>>(ff, 512, wt_ff2 + i*128*512, e2);
    }
    k_layernorm<float><<<16384,128>>>(x1, x2, fin, lnf_g, lnf_b);
    k_pool<<<32,128>>>(fin, out);
}

// round 17
// speedup vs baseline: 1.3615x; 1.0216x over previous
#include <cuda_runtime.h>
#include <cuda_bf16.h>
#include <math.h>
#include <stdint.h>

// B=8 S=512 FDIM=512 SUB=4 DIM=128 HEADS=8 DH=64 INNER=512
// T=2176 (2048+128 mem), NB=34, N_HASHES=4, BUCKET=64, C=136, 4T=8704

__device__ float g_x1 [8*2048*128];
__device__ float g_x2 [8*2048*128];
__device__ float g_fin[8*2048*128];
__device__ float g_aq [8*2176*128];              // fp32 LN out (feeds rv GEMM)
__device__ __nv_bfloat16 g_aqh[8*2176*128];      // bf16 copy for qk/v GEMMs
__device__ __nv_bfloat16 g_ain[8*2048*128];      // bf16 ff1 input
__device__ __nv_bfloat16 g_am [8*2048*512];      // bf16 merged attention output
__device__ __nv_bfloat16 g_ff [8*2048*512];      // bf16 gelu output
__device__ float g_qk [8*8*2176*64];
__device__ float g_v  [8*8*2176*64];
__device__ float g_rv [8*2176*512];              // bucket rotation output
__device__ float g_rotm[2][128*512];             // W_qk[:,LSH] @ rot, padded to 512
__device__ int   g_bkt [48*8704];
__device__ int   g_st  [48*8704];
__device__ int   g_undo[48*8704];
__device__ float g_so  [48*8704*64];
__device__ float g_slog[48*8704];
__device__ __nv_bfloat16 g_wt_out[2][128*512];   // w_out^T  [n=128][k=512]
__device__ __nv_bfloat16 g_wt_ff1[2][512*128];   // ff_w1^T  [n=512][k=128]
__device__ __nv_bfloat16 g_wt_ff2[2][128*512];   // ff_w2^T  [n=128][k=512]
__device__ __nv_bfloat16 g_wt_v  [2][512*128];   // w_v^T    [n=512][k=128]
__device__ __nv_bfloat16 g_wt_qk [2][512*128];   // w_qk^T   [n=512][k=128]

__device__ __forceinline__ uint32_t smem_u32(const void* p){
    uint32_t a;
    asm("{ .reg .u64 t; cvta.to.shared.u64 t, %1; cvt.u32.u64 %0, t; }" : "=r"(a) : "l"(p));
    return a;
}
__device__ __forceinline__ void ldm4(uint32_t& r0, uint32_t& r1, uint32_t& r2, uint32_t& r3,
                                     uint32_t addr){
    asm volatile("ldmatrix.sync.aligned.m8n8.x4.shared.b16 {%0,%1,%2,%3}, [%4];"
        : "=r"(r0),"=r"(r1),"=r"(r2),"=r"(r3) : "r"(addr));
}
__device__ __forceinline__ void ldm4t(uint32_t& r0, uint32_t& r1, uint32_t& r2, uint32_t& r3,
                                      uint32_t addr){
    asm volatile("ldmatrix.sync.aligned.m8n8.x4.trans.shared.b16 {%0,%1,%2,%3}, [%4];"
        : "=r"(r0),"=r"(r1),"=r"(r2),"=r"(r3) : "r"(addr));
}
__device__ __forceinline__ void mma16816(float* c, const uint32_t* a, const uint32_t* b){
    asm volatile("mma.sync.aligned.m16n8k16.row.col.f32.bf16.bf16.f32 "
        "{%0,%1,%2,%3}, {%4,%5,%6,%7}, {%8,%9}, {%0,%1,%2,%3};"
        : "+f"(c[0]),"+f"(c[1]),"+f"(c[2]),"+f"(c[3])
        : "r"(a[0]),"r"(a[1]),"r"(a[2]),"r"(a[3]), "r"(b[0]),"r"(b[1]));
}
__device__ __forceinline__ uint4 f8_to_bf8(float4 a, float4 b){
    __nv_bfloat162 h0 = __floats2bfloat162_rn(a.x, a.y);
    __nv_bfloat162 h1 = __floats2bfloat162_rn(a.z, a.w);
    __nv_bfloat162 h2 = __floats2bfloat162_rn(b.x, b.y);
    __nv_bfloat162 h3 = __floats2bfloat162_rn(b.z, b.w);
    uint4 r;
    r.x = *(uint32_t*)&h0; r.y = *(uint32_t*)&h1;
    r.z = *(uint32_t*)&h2; r.w = *(uint32_t*)&h3;
    return r;
}

// ---- all weight converts in one launch: 10 matrices x 65536 elements ----
__global__ void __launch_bounds__(256) k_wcvt_all(const float* __restrict__ w_out,
                                                  const float* __restrict__ ff_w1,
                                                  const float* __restrict__ ff_w2,
                                                  const float* __restrict__ w_v,
                                                  const float* __restrict__ w_qk){
    int idx = blockIdx.x*256 + threadIdx.x;      // 10*65536
    int sel = idx >> 16, local = idx & 65535;
    int i = sel / 5, m = sel % 5;
    const float* src; __nv_bfloat16* dst; int n, k;
    if (m == 0){ src = w_out + i*65536; dst = g_wt_out[i];
                 n = local >> 9; k = local & 511;          // dst [128][512], src [512][128]
                 dst[local] = __float2bfloat16(src[k*128 + n]); return; }
    if (m == 1){ src = ff_w1 + i*65536; dst = g_wt_ff1[i];
                 n = local >> 7; k = local & 127;          // dst [512][128], src [128][512]
                 dst[local] = __float2bfloat16(src[k*512 + n]); return; }
    if (m == 2){ src = ff_w2 + i*65536; dst = g_wt_ff2[i];
                 n = local >> 9; k = local & 511;
                 dst[local] = __float2bfloat16(src[k*128 + n]); return; }
    if (m == 3){ src = w_v + i*65536; dst = g_wt_v[i];
                 n = local >> 7; k = local & 127;
                 dst[local] = __float2bfloat16(src[k*512 + n]); return; }
    { src = w_qk + i*65536; dst = g_wt_qk[i];
      n = local >> 7; k = local & 127;
      dst[local] = __float2bfloat16(src[k*512 + n]); }
}

// ---- build rotation-combined matrix: M[i][k][n] = sum_f w_qk[k][128+head*64+f]*rot[f][r] ----
__global__ void __launch_bounds__(256) k_mkrot(const float* __restrict__ w_qk,
                                               const float* __restrict__ rot){
    int idx = blockIdx.x*256 + threadIdx.x;      // 2*65536
    int i = idx >> 16, local = idx & 65535;
    int k = local >> 9, n = local & 511;
    float s = 0.f;
    if (n < 408){
        int head = n / 68, r = n - head*68;
        const float* wp = w_qk + i*65536 + k*512 + 128 + head*64;
        const float* rp = rot  + i*64*68 + r;
        for (int f = 0; f < 64; f++) s += wp[f]*rp[f*68];
    }
    g_rotm[i][k*512 + n] = s;
}

// ====== HMMA GEMM ======
struct EAddBias {
    float* out; const float* bias; int ld;
    __device__ __forceinline__ void operator()(int m, int n, float v) const {
        out[m*ld + n] += v + bias[n];
    }
};
struct EGelu {
    __nv_bfloat16* out; const float* bias;
    __device__ __forceinline__ void operator()(int m, int n, float v) const {
        float h = v + bias[n];
        out[m*512 + n] = __float2bfloat16(0.5f*h*(1.0f + erff(h*0.7071067811865475f)));
    }
};
struct EQKV {
    float* out;
    __device__ __forceinline__ void operator()(int m, int n, float v) const {
        int b = m / 2176, t = m - b*2176;
        out[(((b<<3) + (n>>6))*2176 + t)*64 + (n & 63)] = v;
    }
};
struct EStore {
    float* out;
    __device__ __forceinline__ void operator()(int m, int n, float v) const {
        out[m*512 + n] = v;
    }
};

template<class EP>
__global__ void __launch_bounds__(256) k_tgemm(const __nv_bfloat16* __restrict__ A, int K,
                                               const __nv_bfloat16* __restrict__ BT,
                                               EP ep){
    __shared__ __nv_bfloat16 As[128][72];
    __shared__ __nv_bfloat16 Bs[128][72];
    int tid = threadIdx.x, wid = tid >> 5, lane = tid & 31;
    int wm = wid >> 1, wn = wid & 1;
    int bm = blockIdx.y*128, bn = blockIdx.x*128;
    float acc[2][8][4] = {};
    int nc = K >> 6;
    for (int kc = 0; kc < nc; kc++){
        for (int p = tid; p < 1024; p += 256){
            int row = p >> 3, q = p & 7;
            *(uint4*)&As[row][q*8] = *(const uint4*)(A  + (size_t)(bm+row)*K + kc*64 + q*8);
            *(uint4*)&Bs[row][q*8] = *(const uint4*)(BT + (size_t)(bn+row)*K + kc*64 + q*8);
        }
        __syncthreads();
#pragma unroll
        for (int s = 0; s < 4; s++){
            uint32_t af[2][4];
#pragma unroll
            for (int mt = 0; mt < 2; mt++){
                uint32_t addr = smem_u32(&As[wm*32 + mt*16 + (lane & 15)][s*16 + (lane >> 4)*8]);
                ldm4(af[mt][0], af[mt][1], af[mt][2], af[mt][3], addr);
            }
            uint32_t bf[8][2];
#pragma unroll
            for (int nt16 = 0; nt16 < 4; nt16++){
                int mi = lane >> 3;
                uint32_t addr = smem_u32(&Bs[wn*64 + nt16*16 + (mi >> 1)*8 + (lane & 7)][s*16 + (mi & 1)*8]);
                uint32_t r0,r1,r2,r3;
                ldm4(r0,r1,r2,r3, addr);
                bf[nt16*2][0]   = r0; bf[nt16*2][1]   = r1;
                bf[nt16*2+1][0] = r2; bf[nt16*2+1][1] = r3;
            }
#pragma unroll
            for (int mt = 0; mt < 2; mt++)
#pragma unroll
                for (int nt = 0; nt < 8; nt++)
                    mma16816(acc[mt][nt], af[mt], bf[nt]);
        }
        __syncthreads();
    }
#pragma unroll
    for (int mt = 0; mt < 2; mt++){
#pragma unroll
        for (int nt = 0; nt < 8; nt++){
            int m = bm + wm*32 + mt*16 + (lane >> 2);
            int n = bn + wn*64 + nt*8 + (lane & 3)*2;
            ep(m,   n,   acc[mt][nt][0]);
            ep(m,   n+1, acc[mt][nt][1]);
            ep(m+8, n,   acc[mt][nt][2]);
            ep(m+8, n+1, acc[mt][nt][3]);
        }
    }
}

// ================= rest of pipeline =================
__global__ void __launch_bounds__(256) k_embed(const float* __restrict__ feat){
    int idx = blockIdx.x*256 + threadIdx.x;
    int b = idx >> 18, r = idx & 262143;
    int t = r >> 7, d = r & 127;
    int s = t >> 2, f = ((t & 3) << 7) + d;
    float inv = expf(-(2.0f*(float)f/512.0f)*9.210340371976184f);
    float ang = (float)s * inv;
    float pe = (f & 1) ? cosf(ang) : sinf(ang);
    float v = feat[(b*512 + s)*512 + f] + pe;
    g_x1[idx] = v; g_x2[idx] = v;
}

template<typename OutT>
__global__ void __launch_bounds__(128) k_layernorm(const float* __restrict__ in1,
                                                   const float* __restrict__ in2,
                                                   OutT* __restrict__ outp,
                                                   const float* __restrict__ gam,
                                                   const float* __restrict__ bet){
    int row = blockIdx.x, d = threadIdx.x;
    float x = in1[row*128 + d];
    if (in2) x = 0.5f*(x + in2[row*128 + d]);
    __shared__ float sh[4];
    float s = x;
#pragma unroll
    for (int o=16;o>0;o>>=1) s += __shfl_xor_sync(0xffffffffu, s, o);
    if ((d & 31) == 0) sh[d>>5] = s;
    __syncthreads();
    float mean = (sh[0]+sh[1]+sh[2]+sh[3]) * (1.0f/128.0f);
    float c = x - mean;
    __syncthreads();
    float v = c*c;
#pragma unroll
    for (int o=16;o>0;o>>=1) v += __shfl_xor_sync(0xffffffffu, v, o);
    if ((d & 31) == 0) sh[d>>5] = v;
    __syncthreads();
    float var = (sh[0]+sh[1]+sh[2]+sh[3]) * (1.0f/128.0f);
    outp[row*128 + d] = (OutT)(c * rsqrtf(var + 1e-5f) * gam[d] + bet[d]);
}

// LN -> packed fp32 + bf16 (rows b*2048+t -> b*2176+t)
__global__ void __launch_bounds__(128) k_ln_qkv(const float* __restrict__ in1,
                                                const float* __restrict__ gam,
                                                const float* __restrict__ bet){
    int row = blockIdx.x, d = threadIdx.x;
    float x = in1[row*128 + d];
    __shared__ float sh[4];
    float s = x;
#pragma unroll
    for (int o=16;o>0;o>>=1) s += __shfl_xor_sync(0xffffffffu, s, o);
    if ((d & 31) == 0) sh[d>>5] = s;
    __syncthreads();
    float mean = (sh[0]+sh[1]+sh[2]+sh[3]) * (1.0f/128.0f);
    float c = x - mean;
    __syncthreads();
    float v = c*c;
#pragma unroll
    for (int o=16;o>0;o>>=1) v += __shfl_xor_sync(0xffffffffu, v, o);
    if ((d & 31) == 0) sh[d>>5] = v;
    __syncthreads();
    float var = (sh[0]+sh[1]+sh[2]+sh[3]) * (1.0f/128.0f);
    float y = c * rsqrtf(var + 1e-5f) * gam[d] + bet[d];
    int orow = row + (row>>11)*128;
    g_aq [orow*128 + d] = y;
    g_aqh[orow*128 + d] = __float2bfloat16(y);
}

__global__ void __launch_bounds__(256) k_memfill(const float* __restrict__ mem){
    int idx = blockIdx.x*256 + threadIdx.x;     // 8*128*128
    int b = idx >> 14, r = idx & 16383;
    float x = mem[r];
    int o = (b*2176 + 2048)*128 + r;
    g_aq [o] = x;
    g_aqh[o] = __float2bfloat16(x);
}

// fp32 GEMM (rv only — feeds LSH argmax)
template<class EP>
__global__ void __launch_bounds__(256) k_gemm(const float* __restrict__ A, int K,
                                              const float* __restrict__ Bm, int N,
                                              EP ep){
    __shared__ float As[2][16][132];
    __shared__ float Bs[2][16][132];
    int bm = blockIdx.y*128, bn = blockIdx.x*128;
    int tid = threadIdx.x, tx = tid & 15, ty = tid >> 4;
    int arow = tid >> 1, aq = tid & 1;
    int bkk = tid >> 4, bv = tid & 15;
    float acc[8][8] = {};
    const float* Arow = A + (bm+arow)*K;
    {
        float4 a0 = *(const float4*)(Arow + aq*4);
        float4 a1 = *(const float4*)(Arow + (aq+2)*4);
        float4 b0 = *(const float4*)(Bm + bkk*N + bn + bv*4);
        float4 b1 = *(const float4*)(Bm + bkk*N + bn + bv*4 + 64);
        As[0][aq*4+0][arow] = a0.x; As[0][aq*4+1][arow] = a0.y;
        As[0][aq*4+2][arow] = a0.z; As[0][aq*4+3][arow] = a0.w;
        As[0][aq*4+8][arow] = a1.x; As[0][aq*4+9][arow] = a1.y;
        As[0][aq*4+10][arow] = a1.z; As[0][aq*4+11][arow] = a1.w;
        *(float4*)&Bs[0][bkk][bv*4]      = b0;
        *(float4*)&Bs[0][bkk][bv*4 + 64] = b1;
    }
    __syncthreads();
    int nt = K >> 4;
    for (int t = 0; t < nt; t++){
        int cur = t & 1, nxt = cur ^ 1;
        float4 na0, na1, nb0, nb1;
        if (t+1 < nt){
            int k0 = (t+1) << 4;
            na0 = *(const float4*)(Arow + k0 + aq*4);
            na1 = *(const float4*)(Arow + k0 + (aq+2)*4);
            nb0 = *(const float4*)(Bm + (k0+bkk)*N + bn + bv*4);
            nb1 = *(const float4*)(Bm + (k0+bkk)*N + bn + bv*4 + 64);
        }
#pragma unroll
        for (int kk=0;kk<16;kk++){
            float4 a0 = *(float4*)&As[cur][kk][ty*8];
            float4 a1 = *(float4*)&As[cur][kk][ty*8+4];
            float4 b0 = *(float4*)&Bs[cur][kk][tx*8];
            float4 b1 = *(float4*)&Bs[cur][kk][tx*8+4];
            float av[8] = {a0.x,a0.y,a0.z,a0.w,a1.x,a1.y,a1.z,a1.w};
            float bv2[8] = {b0.x,b0.y,b0.z,b0.w,b1.x,b1.y,b1.z,b1.w};
#pragma unroll
            for (int i=0;i<8;i++)
#pragma unroll
                for (int j=0;j<8;j++) acc[i][j] = fmaf(av[i], bv2[j], acc[i][j]);
        }
        if (t+1 < nt){
            As[nxt][aq*4+0][arow] = na0.x; As[nxt][aq*4+1][arow] = na0.y;
            As[nxt][aq*4+2][arow] = na0.z; As[nxt][aq*4+3][arow] = na0.w;
            As[nxt][aq*4+8][arow] = na1.x; As[nxt][aq*4+9][arow] = na1.y;
            As[nxt][aq*4+10][arow] = na1.z; As[nxt][aq*4+11][arow] = na1.w;
            *(float4*)&Bs[nxt][bkk][bv*4]      = nb0;
            *(float4*)&Bs[nxt][bkk][bv*4 + 64] = nb1;
            __syncthreads();
        }
    }
#pragma unroll
    for (int i=0;i<8;i++)
#pragma unroll
        for (int j=0;j<8;j++) ep(bm + ty*8 + i, bn + tx*8 + j, acc[i][j]);
}

// ---- bucket argmax from precomputed rv ----
__global__ void __launch_bounds__(128) k_bkt2(){
    int bh = blockIdx.x, t = blockIdx.y*128 + threadIdx.x;
    int b = bh / 6, head = bh % 6;
    const float* rp = g_rv + (size_t)(b*2176 + t)*512 + head*68;
    float rv[68];
#pragma unroll
    for (int u=0;u<68;u++) rv[u] = rp[u];
#pragma unroll
    for (int h=0; h<4; h++){
        float best = rv[h*17]; int bi = 0;
#pragma unroll
        for (int i=1;i<17;i++){ float v = rv[h*17+i]; if (v > best){ best = v; bi = i; } }
#pragma unroll
        for (int i=0;i<17;i++){ float v = -rv[h*17+i]; if (v > best){ best = v; bi = 17+i; } }
        g_bkt[bh*8704 + h*2176 + t] = bi + h*34;
    }
}

__global__ void __launch_bounds__(64) k_sort(){
    __shared__ int hist[64][136];
    __shared__ int base[136];
    int bh = blockIdx.x, t = threadIdx.x;
    int* hrow = hist[t];
    for (int i=0;i<136;i++) hrow[i] = 0;
    const int* bk = g_bkt + bh*8704;
    int i0 = t*136;
    for (int i=0;i<136;i++) hrow[bk[i0+i]]++;
    __syncthreads();
    for (int c = t; c < 136; c += 64){
        int run = 0;
        for (int tt=0; tt<64; tt++){ int v = hist[tt][c]; hist[tt][c] = run; run += v; }
        base[c] = run;
    }
    __syncthreads();
    if (t == 0){
        int run = 0;
        for (int c=0;c<136;c++){ int v = base[c]; base[c] = run; run += v; }
    }
    __syncthreads();
    for (int i=0;i<136;i++){
        int idx = i0 + i, bb = bk[idx];
        int pos = base[bb] + hrow[bb]; hrow[bb]++;
        g_st  [bh*8704 + pos] = idx % 2176;
        g_undo[bh*8704 + idx] = pos;
    }
}

// ---- LSH chunk attention: HMMA dots + PV ----
__global__ void __launch_bounds__(256) k_lsh_attn(){
    extern __shared__ char smc[];
    __nv_bfloat16* skb = (__nv_bfloat16*)smc;              // [128][72]
    __nv_bfloat16* svb = (__nv_bfloat16*)(smc + 18432);    // [128][72]
    float* sd          = (float*)(smc + 36864);            // [64][128]
    __nv_bfloat16* sp  = (__nv_bfloat16*)(smc + 69632);    // [64][136]
    float* scale       = (float*)(smc + 87040);            // [128]
    int*   skt         = (int*)(smc + 87552);              // [128]
    int bh = blockIdx.x, c = blockIdx.y, tid = threadIdx.x;
    int wid = tid >> 5, lane = tid & 31;
    int base  = bh*8704 + c*64;
    int pbase = bh*8704 + ((c + 135) % 136)*64;
    int b = bh / 6, head = 2 + bh % 6;
    int bhh = (b<<3) + head;
    for (int p = tid; p < 1024; p += 256){
        int row = p >> 3, c8 = p & 7;
        int src = (row < 64) ? g_st[base + row] : g_st[pbase + row - 64];
        const float4* qp = (const float4*)(g_qk + (bhh*2176 + src)*64 + c8*8);
        const float4* vp = (const float4*)(g_v  + (bhh*2176 + src)*64 + c8*8);
        *(uint4*)&skb[row*72 + c8*8] = f8_to_bf8(qp[0], qp[1]);
        *(uint4*)&svb[row*72 + c8*8] = f8_to_bf8(vp[0], vp[1]);
    }
    if (tid < 128)
        skt[tid] = (tid < 64) ? g_st[base + tid] : g_st[pbase + tid - 64];
    __syncthreads();
    if (tid < 128){
        float s = 0.f;
        const uint32_t* rp = (const uint32_t*)(skb + tid*72);
#pragma unroll
        for (int i = 0; i < 32; i++){
            float2 f = __bfloat1622float2(*(const __nv_bfloat162*)&rp[i]);
            s += f.x*f.x + f.y*f.y;
        }
        scale[tid] = 1.0f / fmaxf(sqrtf(s), 1e-12f);
    }
    __syncthreads();
    int wm = wid >> 1, wn = wid & 1;
    {
        float dacc[8][4] = {};
#pragma unroll
        for (int s = 0; s < 4; s++){
            uint32_t af[4];
            ldm4(af[0],af[1],af[2],af[3],
                 smem_u32(&skb[(wm*16 + (lane & 15))*72 + s*16 + (lane >> 4)*8]));
            uint32_t bf[8][2];
#pragma unroll
            for (int nt16 = 0; nt16 < 4; nt16++){
                int mi = lane >> 3;
                uint32_t r0,r1,r2,r3;
                ldm4(r0,r1,r2,r3,
                     smem_u32(&skb[(wn*64 + nt16*16 + (mi >> 1)*8 + (lane & 7))*72 + s*16 + (mi & 1)*8]));
                bf[nt16*2][0]   = r0; bf[nt16*2][1]   = r1;
                bf[nt16*2+1][0] = r2; bf[nt16*2+1][1] = r3;
            }
#pragma unroll
            for (int nt = 0; nt < 8; nt++)
                mma16816(dacc[nt], af, bf[nt]);
        }
#pragma unroll
        for (int nt = 0; nt < 8; nt++){
            int row = wm*16 + (lane >> 2);
            int col = wn*64 + nt*8 + (lane & 3)*2;
#pragma unroll
            for (int e = 0; e < 4; e++){
                int r = row + (e >> 1)*8, cc = col + (e & 1);
                int tq = skt[r], tk = skt[cc];
                float v = dacc[nt][e]*scale[cc]*0.125f;
                if (tq < tk)       v = -1e9f;
                else if (tq == tk) v = -5e4f;
                sd[r*128 + cc] = v;
            }
        }
    }
    __syncthreads();
    {
        int warp = wid, ln = lane;
        for (int rr=0; rr<8; rr++){
            int row = warp*8 + rr;
            float d0[4];
#pragma unroll
            for (int j=0;j<4;j++) d0[j] = sd[row*128 + ln + 32*j];
            float m = fmaxf(fmaxf(d0[0],d0[1]), fmaxf(d0[2],d0[3]));
#pragma unroll
            for (int o=16;o>0;o>>=1) m = fmaxf(m, __shfl_xor_sync(0xffffffffu, m, o));
            float p[4], s = 0.f;
#pragma unroll
            for (int j=0;j<4;j++){ p[j] = __expf(d0[j]-m); s += p[j]; }
#pragma unroll
            for (int o=16;o>0;o>>=1) s += __shfl_xor_sync(0xffffffffu, s, o);
            float inv = 1.0f/s;
#pragma unroll
            for (int j=0;j<4;j++) sp[row*136 + ln + 32*j] = __float2bfloat16(p[j]*inv);
            if (ln == 0) g_slog[base + row] = m + __logf(s);
        }
    }
    __syncthreads();
    {
        float pacc[4][4] = {};
#pragma unroll
        for (int s = 0; s < 8; s++){
            uint32_t af[4];
            ldm4(af[0],af[1],af[2],af[3],
                 smem_u32(&sp[(wm*16 + (lane & 15))*136 + s*16 + (lane >> 4)*8]));
            uint32_t bf[4][2];
#pragma unroll
            for (int nt16 = 0; nt16 < 2; nt16++){
                int mi = lane >> 3;
                uint32_t r0,r1,r2,r3;
                ldm4t(r0,r1,r2,r3,
                      smem_u32(&svb[(s*16 + (mi & 1)*8 + (lane & 7))*72 + wn*32 + nt16*16 + (mi >> 1)*8]));
                bf[nt16*2][0]   = r0; bf[nt16*2][1]   = r1;
                bf[nt16*2+1][0] = r2; bf[nt16*2+1][1] = r3;
            }
#pragma unroll
            for (int nt = 0; nt < 4; nt++)
                mma16816(pacc[nt], af, bf[nt]);
        }
#pragma unroll
        for (int nt = 0; nt < 4; nt++){
            int row = wm*16 + (lane >> 2);
            int col = wn*32 + nt*8 + (lane & 3)*2;
            g_so[(base + row)*64 + col]     = pacc[nt][0];
            g_so[(base + row)*64 + col + 1] = pacc[nt][1];
            g_so[(base + row + 8)*64 + col]     = pacc[nt][2];
            g_so[(base + row + 8)*64 + col + 1] = pacc[nt][3];
        }
    }
}

__global__ void __launch_bounds__(256) k_unsort(){
    int bh = blockIdx.y, tid = threadIdx.x;
    int g = tid >> 6, d = tid & 63;
    int t = blockIdx.x*4 + g;
    __shared__ int pos[4][4]; __shared__ float w[4][4];
    if (d < 4){
        int p = g_undo[bh*8704 + d*2176 + t];
        pos[g][d] = p; w[g][d] = g_slog[bh*8704 + p];
    }
    __syncthreads();
    if (d == 0){
        float m = fmaxf(fmaxf(w[g][0],w[g][1]), fmaxf(w[g][2],w[g][3]));
        float s = 0.f;
        for (int h=0;h<4;h++){ w[g][h] = __expf(w[g][h]-m); s += w[g][h]; }
        float inv = 1.0f/s;
        for (int h=0;h<4;h++) w[g][h] *= inv;
    }
    __syncthreads();
    float o = 0.f;
    for (int h=0;h<4;h++) o += w[g][h]*g_so[(bh*8704 + pos[g][h])*64 + d];
    int b = bh / 6, head = 2 + bh % 6;
    g_am[(b*2048 + t)*512 + head*64 + d] = __float2bfloat16(o);
}

// ---- local windowed attention: HMMA dots + PV, 64 q x 256 kv ----
__global__ void __launch_bounds__(256) k_local_attn(){
    extern __shared__ char smc[];
    __nv_bfloat16* skv = (__nv_bfloat16*)smc;              // [256][72]
    __nv_bfloat16* svb = (__nv_bfloat16*)(smc + 36864);    // [256][72]
    float* sd          = (float*)(smc + 73728);            // [64][256]
    __nv_bfloat16* sp  = (__nv_bfloat16*)(smc + 139264);   // [64][264]
    float* scale       = (float*)(smc + 173056);           // [256]
    int bh = blockIdx.x, b = bh >> 1, head = bh & 1;
    int win = blockIdx.y, half = blockIdx.z;
    int tid = threadIdx.x, wid = tid >> 5, lane = tid & 31;
    const float* qbase = g_qk + (((b<<3) + head)*2176)*64;
    const float* vbase = g_v  + (((b<<3) + head)*2176)*64;
    int q0 = win*128 + half*64;
    int qrow = 128 + half*64;
    for (int p = tid; p < 2048; p += 256){
        int row = p >> 3, c8 = p & 7;
        uint4 kv, vv;
        if (row < 128 && win == 0){
            kv = make_uint4(0,0,0,0); vv = kv;
        } else {
            int t = (row < 128) ? (win-1)*128 + row : win*128 + row - 128;
            const float4* qp = (const float4*)(qbase + t*64 + c8*8);
            const float4* vp = (const float4*)(vbase + t*64 + c8*8);
            kv = f8_to_bf8(qp[0], qp[1]);
            vv = f8_to_bf8(vp[0], vp[1]);
        }
        *(uint4*)&skv[row*72 + c8*8] = kv;
        *(uint4*)&svb[row*72 + c8*8] = vv;
    }
    __syncthreads();
    {
        float s = 0.f;
        const uint32_t* rp = (const uint32_t*)(skv + tid*72);
#pragma unroll
        for (int i = 0; i < 32; i++){
            float2 f = __bfloat1622float2(*(const __nv_bfloat162*)&rp[i]);
            s += f.x*f.x + f.y*f.y;
        }
        scale[tid] = 1.0f / fmaxf(sqrtf(s), 1e-12f);
    }
    __syncthreads();
    int wm = wid & 3, wn = wid >> 2;
    {
        float dacc[16][4] = {};
#pragma unroll
        for (int s = 0; s < 4; s++){
            uint32_t af[4];
            ldm4(af[0],af[1],af[2],af[3],
                 smem_u32(&skv[(qrow + wm*16 + (lane & 15))*72 + s*16 + (lane >> 4)*8]));
            uint32_t bf[16][2];
#pragma unroll
            for (int nt16 = 0; nt16 < 8; nt16++){
                int mi = lane >> 3;
                uint32_t r0,r1,r2,r3;
                ldm4(r0,r1,r2,r3,
                     smem_u32(&skv[(wn*128 + nt16*16 + (mi >> 1)*8 + (lane & 7))*72 + s*16 + (mi & 1)*8]));
                bf[nt16*2][0]   = r0; bf[nt16*2][1]   = r1;
                bf[nt16*2+1][0] = r2; bf[nt16*2+1][1] = r3;
            }
#pragma unroll
            for (int nt = 0; nt < 16; nt++)
                mma16816(dacc[nt], af, bf[nt]);
        }
#pragma unroll
        for (int nt = 0; nt < 16; nt++){
            int row = wm*16 + (lane >> 2);
            int col = wn*128 + nt*8 + (lane & 3)*2;
#pragma unroll
            for (int e = 0; e < 4; e++){
                int r = row + (e >> 1)*8, jc = col + (e & 1);
                int tq = q0 + r;
                float v = dacc[nt][e]*scale[jc]*0.125f;
                if (jc < 128){
                    if (win == 0) v = -1e9f;
                    else {
                        int tk = (win-1)*128 + jc;
                        if (tq == tk) v = -5e4f; else if (tq < tk) v = -1e9f;
                    }
                } else {
                    int tk = win*128 + jc - 128;
                    if (tq == tk) v = -5e4f; else if (tq < tk) v = -1e9f;
                }
                sd[r*256 + jc] = v;
            }
        }
    }
    __syncthreads();
    {
        int warp = wid, ln = lane;
        for (int rr=0; rr<8; rr++){
            int row = warp*8 + rr;
            float d0[8];
#pragma unroll
            for (int j=0;j<8;j++) d0[j] = sd[row*256 + ln + 32*j];
            float m = d0[0];
#pragma unroll
            for (int j=1;j<8;j++) m = fmaxf(m, d0[j]);
#pragma unroll
            for (int o=16;o>0;o>>=1) m = fmaxf(m, __shfl_xor_sync(0xffffffffu, m, o));
            float p[8], s = 0.f;
#pragma unroll
            for (int j=0;j<8;j++){ p[j] = __expf(d0[j]-m); s += p[j]; }
#pragma unroll
            for (int o=16;o>0;o>>=1) s += __shfl_xor_sync(0xffffffffu, s, o);
            float inv = 1.0f/s;
#pragma unroll
            for (int j=0;j<8;j++) sp[row*264 + ln + 32*j] = __float2bfloat16(p[j]*inv);
        }
    }
    __syncthreads();
    {
        int wm2 = wid & 3, wn2 = wid >> 2;
        float pacc[4][4] = {};
#pragma unroll
        for (int s = 0; s < 16; s++){
            uint32_t af[4];
            ldm4(af[0],af[1],af[2],af[3],
                 smem_u32(&sp[(wm2*16 + (lane & 15))*264 + s*16 + (lane >> 4)*8]));
            uint32_t bf[4][2];
#pragma unroll
            for (int nt16 = 0; nt16 < 2; nt16++){
                int mi = lane >> 3;
                uint32_t r0,r1,r2,r3;
                ldm4t(r0,r1,r2,r3,
                      smem_u32(&svb[(s*16 + (mi & 1)*8 + (lane & 7))*72 + wn2*32 + nt16*16 + (mi >> 1)*8]));
                bf[nt16*2][0]   = r0; bf[nt16*2][1]   = r1;
                bf[nt16*2+1][0] = r2; bf[nt16*2+1][1] = r3;
            }
#pragma unroll
            for (int nt = 0; nt < 4; nt++)
                mma16816(pacc[nt], af, bf[nt]);
        }
#pragma unroll
        for (int nt = 0; nt < 4; nt++){
            int row = wm2*16 + (lane >> 2);
            int col = wn2*32 + nt*8 + (lane & 3)*2;
#pragma unroll
            for (int e = 0; e < 4; e++){
                int r = row + (e >> 1)*8, cc = col + (e & 1);
                int t = q0 + r;
                if (t < 2048)
                    g_am[(b*2048 + t)*512 + head*64 + cc] = __float2bfloat16(pacc[nt][e]);
            }
        }
    }
}

__global__ void __launch_bounds__(128) k_pool(const float* __restrict__ in, float* __restrict__ out){
    int b = blockIdx.x >> 2, sub = blockIdx.x & 3, d = threadIdx.x;
    const float* p = in + (b*2048 + sub)*128 + d;
    float s = 0.f;
    for (int i=0;i<512;i++) s += p[i*512];
    out[b*512 + sub*128 + d] = s * (1.0f/512.0f);
}

extern "C" void kernel_launch(void* const* d_in, const int* in_sizes, int n_in,
                              void* d_out, int out_size){
    const float* features  = (const float*)d_in[0];
    const float* w_qk      = (const float*)d_in[1];
    const float* w_v       = (const float*)d_in[2];
    const float* mem_kv    = (const float*)d_in[3];
    const float* w_out     = (const float*)d_in[4];
    const float* b_out     = (const float*)d_in[5];
    const float* ln1_g     = (const float*)d_in[6];
    const float* ln1_b     = (const float*)d_in[7];
    const float* ff_w1     = (const float*)d_in[8];
    const float* ff_b1     = (const float*)d_in[9];
    const float* ff_w2     = (const float*)d_in[10];
    const float* ff_b2     = (const float*)d_in[11];
    const float* ln2_g     = (const float*)d_in[12];
    const float* ln2_b     = (const float*)d_in[13];
    const float* lnf_g     = (const float*)d_in[14];
    const float* lnf_b     = (const float*)d_in[15];
    const float* rotations = (const float*)d_in[16];
    float* out = (float*)d_out;

    float *x1,*x2,*fin,*aq,*qk,*vv,*rv,*rotm;
    __nv_bfloat16 *aqh,*ain,*am,*ff,*wt_out,*wt_ff1,*wt_ff2,*wt_v,*wt_qk;
    cudaGetSymbolAddress((void**)&x1,  g_x1);
    cudaGetSymbolAddress((void**)&x2,  g_x2);
    cudaGetSymbolAddress((void**)&fin, g_fin);
    cudaGetSymbolAddress((void**)&aq,  g_aq);
    cudaGetSymbolAddress((void**)&aqh, g_aqh);
    cudaGetSymbolAddress((void**)&qk,  g_qk);
    cudaGetSymbolAddress((void**)&vv,  g_v);
    cudaGetSymbolAddress((void**)&rv,  g_rv);
    cudaGetSymbolAddress((void**)&rotm, g_rotm);
    cudaGetSymbolAddress((void**)&ain, g_ain);
    cudaGetSymbolAddress((void**)&am,  g_am);
    cudaGetSymbolAddress((void**)&ff,  g_ff);
    cudaGetSymbolAddress((void**)&wt_out, g_wt_out);
    cudaGetSymbolAddress((void**)&wt_ff1, g_wt_ff1);
    cudaGetSymbolAddress((void**)&wt_ff2, g_wt_ff2);
    cudaGetSymbolAddress((void**)&wt_v,   g_wt_v);
    cudaGetSymbolAddress((void**)&wt_qk,  g_wt_qk);

    const int LSH_SMEM = 88064;
    const int LOC_SMEM = 174080;
    cudaFuncSetAttribute(k_lsh_attn,   cudaFuncAttributeMaxDynamicSharedMemorySize, LSH_SMEM);
    cudaFuncSetAttribute(k_local_attn, cudaFuncAttributeMaxDynamicSharedMemorySize, LOC_SMEM);

    k_wcvt_all<<<(10*65536)/256,256>>>(w_out, ff_w1, ff_w2, w_v, w_qk);
    k_mkrot<<<(2*65536)/256,256>>>(w_qk, rotations);
    k_embed<<<8192, 256>>>(features);

    for (int i = 0; i < 2; i++){
        k_ln_qkv<<<16384,128>>>(x2, ln1_g + i*128, ln1_b + i*128);
        k_memfill<<<512,256>>>(mem_kv + i*128*128);
        EQKV eq; eq.out = qk;
        EQKV ev; ev.out = vv;
        k_tgemm<<<dim3(4,136),256>>>(aqh, 128, wt_qk + i*512*128, eq);
        k_tgemm<<<dim3(4,136),256>>>(aqh, 128, wt_v  + i*512*128, ev);
        EStore es; es.out = rv;
        k_gemm<<<dim3(4,136),256>>>(aq, 128, rotm + i*128*512, 512, es);
        k_local_attn<<<dim3(16,17,2),256,LOC_SMEM>>>();
        k_bkt2<<<dim3(48,17),128>>>();
        k_sort<<<48,64>>>();
        k_lsh_attn<<<dim3(48,136),256,LSH_SMEM>>>();
        k_unsort<<<dim3(512,48),256>>>();
        EAddBias e1; e1.out = x1; e1.bias = b_out + i*128; e1.ld = 128;
        k_tgemm<<<dim3(1,128),256>>>(am, 512, wt_out + i*128*512, e1);
        k_layernorm<__nv_bfloat16><<<16384,128>>>(x1, (const float*)0, ain, ln2_g + i*128, ln2_b + i*128);
        EGelu eg; eg.out = ff; eg.bias = ff_b1 + i*512;
        k_tgemm<<<dim3(4,128),256>>>(ain, 128, wt_ff1 + i*512*128, eg);
        EAddBias e2; e2.out = x2; e2.bias = ff_b2 + i*128; e2.ld = 128;
        k_tgemm<<<dim3(1,128),256>>>(ff, 512, wt_ff2 + i*128*512, e2);
    }
    k_layernorm<float><<<16384,128>>>(x1, x2, fin, lnf_g, lnf_b);
    k_pool<<<32,128>>>(fin, out);
}